// round 7
// baseline (speedup 1.0000x reference)
#include <cuda_runtime.h>
#include <cuda_bf16.h>
#include <cstdint>
#include <cfloat>

#define N_NODES 100000
#define N_EDGES 500000
#define N_REL 4
#define N_LAYERS 4
#define IN_FEAT 64
#define EMB 128
#define N_GRAPHS 64
#define SCAN_NB 98   // ceil(100000/1024)

// ---------------- scratch (device globals; no allocation allowed) ----------------
__device__ float g_h[(size_t)N_NODES * EMB];                 // final-layer h (for pool)
__device__ float g_out[(size_t)N_NODES * EMB];               // root accumulator
__device__ float g_tmp[(size_t)N_REL * N_NODES * EMB];       // per-relation conv outputs
__device__ __nv_bfloat16 g_h_hi[(size_t)N_NODES * EMB];
__device__ __nv_bfloat16 g_h_lo[(size_t)N_NODES * EMB];
__device__ __nv_bfloat16 g_x_hi[(size_t)N_NODES * IN_FEAT];
__device__ __nv_bfloat16 g_x_lo[(size_t)N_NODES * IN_FEAT];
// 21 weight matrices, transposed [N=128][K=128] bf16 (k contiguous):
// slot 0 = emb (K rows 64..127 zero), 1..4 = root, 5..20 = conv (l*4+r)
__device__ __nv_bfloat16 g_w_hi[(size_t)21 * 128 * 128];
__device__ __nv_bfloat16 g_w_lo[(size_t)21 * 128 * 128];
__device__ int   g_csr_src[(size_t)N_REL * N_EDGES];
__device__ int   g_deg[(size_t)N_REL * N_NODES];
__device__ int   g_off[(size_t)N_REL * (N_NODES + 1)];
__device__ int   g_cur[(size_t)N_REL * N_NODES];
__device__ int   g_bsum[(size_t)N_REL * 128];

// ---------------- warp-mma helpers (baseline PTX; valid at compute_103) ----------------
__device__ __forceinline__ uint32_t smem_u32(const void* p) {
    uint32_t a;
    asm("{ .reg .u64 t; cvta.to.shared.u64 t, %1; cvt.u32.u64 %0, t; }" : "=r"(a) : "l"(p));
    return a;
}
__device__ __forceinline__ void ldsm4(uint32_t& r0, uint32_t& r1, uint32_t& r2, uint32_t& r3,
                                      uint32_t addr) {
    asm volatile("ldmatrix.sync.aligned.m8n8.x4.shared.b16 {%0,%1,%2,%3}, [%4];"
                 : "=r"(r0), "=r"(r1), "=r"(r2), "=r"(r3) : "r"(addr));
}
__device__ __forceinline__ void mma16816(float* d, const uint32_t* a, const uint32_t* b) {
    asm volatile(
        "mma.sync.aligned.m16n8k16.row.col.f32.bf16.bf16.f32 "
        "{%0,%1,%2,%3}, {%4,%5,%6,%7}, {%8,%9}, {%0,%1,%2,%3};"
        : "+f"(d[0]), "+f"(d[1]), "+f"(d[2]), "+f"(d[3])
        : "r"(a[0]), "r"(a[1]), "r"(a[2]), "r"(a[3]), "r"(b[0]), "r"(b[1]));
}

// ---------------- utility kernels ----------------
__global__ void zero_int_kernel(int* p, int n) {
    int i = blockIdx.x * blockDim.x + threadIdx.x;
    if (i < n) p[i] = 0;
}
__global__ void zero_float_kernel(float* p, int n) {
    int i = blockIdx.x * blockDim.x + threadIdx.x;
    if (i < n) p[i] = 0.0f;
}

__global__ void hist_all_kernel(const int* __restrict__ e0, const int* __restrict__ e1,
                                const int* __restrict__ e2, const int* __restrict__ e3,
                                int* __restrict__ deg) {
    int r = blockIdx.y;
    const int* dst = ((r == 0) ? e0 : (r == 1) ? e1 : (r == 2) ? e2 : e3) + N_EDGES;
    int i = blockIdx.x * 256 + threadIdx.x;
    if (i < N_EDGES) atomicAdd(&deg[(size_t)r * N_NODES + dst[i]], 1);
}

// -------- 3-phase parallel exclusive scan of deg -> off (all relations) --------
__global__ void scan_p1(const int* __restrict__ deg, int* __restrict__ bsum) {
    int r = blockIdx.y, b = blockIdx.x, t = threadIdx.x;
    const int* d = deg + (size_t)r * N_NODES;
    int base = b * 1024 + t * 4;
    int s = 0;
#pragma unroll
    for (int j = 0; j < 4; j++) {
        int idx = base + j;
        if (idx < N_NODES) s += d[idx];
    }
    __shared__ int sm[256];
    sm[t] = s;
    __syncthreads();
    for (int o = 128; o > 0; o >>= 1) {
        if (t < o) sm[t] += sm[t + o];
        __syncthreads();
    }
    if (t == 0) bsum[r * 128 + b] = sm[0];
}
__global__ void scan_p2(int* __restrict__ bsum) {
    __shared__ int sm[512];
    int t = threadIdx.x;
    int r = t >> 7;
    int i = t & 127;
    int v = (i < SCAN_NB) ? bsum[r * 128 + i] : 0;
    sm[t] = v;
    __syncthreads();
    for (int d = 1; d < 128; d <<= 1) {
        int add = (i >= d) ? sm[t - d] : 0;
        __syncthreads();
        sm[t] += add;
        __syncthreads();
    }
    int excl = (i == 0) ? 0 : sm[t - 1];
    if (i < SCAN_NB) bsum[r * 128 + i] = excl;
}
__global__ void scan_p3(const int* __restrict__ deg, const int* __restrict__ bsum,
                        int* __restrict__ off, int* __restrict__ cur) {
    int r = blockIdx.y, b = blockIdx.x, t = threadIdx.x;
    const int* d = deg + (size_t)r * N_NODES;
    int* o = off + (size_t)r * (N_NODES + 1);
    int* c = cur + (size_t)r * N_NODES;
    int base = b * 1024 + t * 4;
    int v[4], pre[4];
    int s = 0;
#pragma unroll
    for (int j = 0; j < 4; j++) {
        int idx = base + j;
        v[j] = (idx < N_NODES) ? d[idx] : 0;
        pre[j] = s;
        s += v[j];
    }
    __shared__ int sm[256];
    sm[t] = s;
    __syncthreads();
    for (int dd = 1; dd < 256; dd <<= 1) {
        int add = (t >= dd) ? sm[t - dd] : 0;
        __syncthreads();
        sm[t] += add;
        __syncthreads();
    }
    int texcl = (t == 0) ? 0 : sm[t - 1];
    int boff = bsum[r * 128 + b];
#pragma unroll
    for (int j = 0; j < 4; j++) {
        int idx = base + j;
        if (idx < N_NODES) {
            int val = boff + texcl + pre[j];
            o[idx] = val;
            c[idx] = val;
        }
    }
    if (b == SCAN_NB - 1 && t == 255) o[N_NODES] = boff + sm[255];
}

__global__ void fill_all_kernel(const int* __restrict__ e0, const int* __restrict__ e1,
                                const int* __restrict__ e2, const int* __restrict__ e3,
                                int* __restrict__ cur, int* __restrict__ csr) {
    int r = blockIdx.y;
    const int* eptr = (r == 0) ? e0 : (r == 1) ? e1 : (r == 2) ? e2 : e3;
    int i = blockIdx.x * 256 + threadIdx.x;
    if (i < N_EDGES) {
        int dnode = eptr[N_EDGES + i];
        int pos = atomicAdd(&cur[(size_t)r * N_NODES + dnode], 1);
        csr[(size_t)r * N_EDGES + pos] = eptr[i];
    }
}

// ---------------- fp32 -> bf16 hi/lo split kernels ----------------
__global__ void split_x_kernel(const float* __restrict__ x,
                               __nv_bfloat16* __restrict__ hi,
                               __nv_bfloat16* __restrict__ lo, int n) {
    int i = blockIdx.x * blockDim.x + threadIdx.x;
    if (i >= n) return;
    float v = x[i];
    __nv_bfloat16 h = __float2bfloat16(v);
    hi[i] = h;
    lo[i] = __float2bfloat16(v - __bfloat162float(h));
}
__global__ void split_w_kernel(const float* __restrict__ emb_w,
                               const float* __restrict__ root_w,
                               const float* __restrict__ conv_w,
                               __nv_bfloat16* __restrict__ whi,
                               __nv_bfloat16* __restrict__ wlo) {
    int idx = blockIdx.x * blockDim.x + threadIdx.x;
    if (idx >= 21 * 128 * 128) return;
    int s = idx >> 14;
    int rem = idx & 16383;
    int n = rem >> 7;
    int k = rem & 127;
    float v;
    if (s == 0)      v = (k < IN_FEAT) ? emb_w[(size_t)k * EMB + n] : 0.0f;
    else if (s <= 4) v = root_w[((size_t)(s - 1) * EMB + k) * EMB + n];
    else             v = conv_w[((size_t)(s - 5) * EMB + k) * EMB + n];
    __nv_bfloat16 h = __float2bfloat16(v);
    whi[idx] = h;
    wlo[idx] = __float2bfloat16(v - __bfloat162float(h));
}

// ---------------- bf16x3 mma.sync GEMM: C[M,128] = A[M,K] @ W^T + bias ----------------
#define BK 32
#define SSTR 40

__global__ __launch_bounds__(256, 2) void gemm_mma(
    const __nv_bfloat16* __restrict__ Ahi, const __nv_bfloat16* __restrict__ Alo,
    int M, int K,
    const __nv_bfloat16* __restrict__ Whi, const __nv_bfloat16* __restrict__ Wlo,
    const float* __restrict__ bias,
    float* __restrict__ C,
    __nv_bfloat16* __restrict__ Ohi, __nv_bfloat16* __restrict__ Olo)
{
    __shared__ __nv_bfloat16 As[128 * SSTR];
    __shared__ __nv_bfloat16 Bs[128 * SSTR];

    int tid = threadIdx.x;
    int wid = tid >> 5;
    int lane = tid & 31;
    int wm = wid & 1;
    int wn = wid >> 1;
    int r0 = blockIdx.x * 128;

    uint32_t as_base = smem_u32(As);
    uint32_t bs_base = smem_u32(Bs);

    float acc[4][4][4];
#pragma unroll
    for (int i = 0; i < 4; i++)
#pragma unroll
        for (int j = 0; j < 4; j++)
#pragma unroll
            for (int q = 0; q < 4; q++) acc[i][j][q] = 0.0f;

    int l_within = lane & 7;
    int l_sel = lane >> 3;

    for (int pass = 0; pass < 3; pass++) {
        const __nv_bfloat16* Asrc = (pass == 2) ? Alo : Ahi;
        const __nv_bfloat16* Bsrc = (pass == 1) ? Wlo : Whi;
        for (int k0 = 0; k0 < K; k0 += BK) {
            __syncthreads();
#pragma unroll
            for (int i = 0; i < 2; i++) {
                int idx = tid * 2 + i;
                int row = idx >> 2;
                int ch = idx & 3;
                uint4 v = make_uint4(0, 0, 0, 0);
                int gr = r0 + row;
                if (gr < M)
                    v = *(const uint4*)(Asrc + (size_t)gr * K + k0 + ch * 8);
                *(uint4*)(&As[row * SSTR + ch * 8]) = v;
            }
#pragma unroll
            for (int i = 0; i < 2; i++) {
                int idx = tid * 2 + i;
                int row = idx >> 2;
                int ch = idx & 3;
                uint4 v = *(const uint4*)(Bsrc + (size_t)row * 128 + k0 + ch * 8);
                *(uint4*)(&Bs[row * SSTR + ch * 8]) = v;
            }
            __syncthreads();

#pragma unroll
            for (int ks = 0; ks < 2; ks++) {
                uint32_t af[4][4];
                uint32_t bf[4][2];
#pragma unroll
                for (int fm = 0; fm < 4; fm++) {
                    int arow = wm * 64 + fm * 16 + (l_sel & 1) * 8 + l_within;
                    int acol = ks * 16 + (l_sel >> 1) * 8;
                    ldsm4(af[fm][0], af[fm][1], af[fm][2], af[fm][3],
                          as_base + (uint32_t)(arow * SSTR + acol) * 2u);
                }
#pragma unroll
                for (int g = 0; g < 2; g++) {
                    int brow = wn * 32 + g * 16 + (l_sel >> 1) * 8 + l_within;
                    int bcol = ks * 16 + (l_sel & 1) * 8;
                    uint32_t r0v, r1v, r2v, r3v;
                    ldsm4(r0v, r1v, r2v, r3v,
                          bs_base + (uint32_t)(brow * SSTR + bcol) * 2u);
                    bf[2 * g + 0][0] = r0v; bf[2 * g + 0][1] = r1v;
                    bf[2 * g + 1][0] = r2v; bf[2 * g + 1][1] = r3v;
                }
#pragma unroll
                for (int fm = 0; fm < 4; fm++)
#pragma unroll
                    for (int fn = 0; fn < 4; fn++)
                        mma16816(acc[fm][fn], af[fm], bf[fn]);
            }
        }
    }

    int qrow = lane >> 2;
    int qcol = (lane & 3) * 2;
#pragma unroll
    for (int fm = 0; fm < 4; fm++) {
#pragma unroll
        for (int half = 0; half < 2; half++) {
            int grow = r0 + wm * 64 + fm * 16 + qrow + half * 8;
            if (grow >= M) continue;
#pragma unroll
            for (int fn = 0; fn < 4; fn++) {
                int col = wn * 32 + fn * 8 + qcol;
                float v0 = acc[fm][fn][half * 2 + 0];
                float v1 = acc[fm][fn][half * 2 + 1];
                if (bias) {
                    v0 += __ldg(&bias[col]);
                    v1 += __ldg(&bias[col + 1]);
                }
                if (C) {
                    float2 fv; fv.x = v0; fv.y = v1;
                    *(float2*)(C + (size_t)grow * EMB + col) = fv;
                }
                if (Ohi) {
                    __nv_bfloat16 h0 = __float2bfloat16(v0);
                    __nv_bfloat16 h1 = __float2bfloat16(v1);
                    __nv_bfloat162 hp; hp.x = h0; hp.y = h1;
                    __nv_bfloat162 lp;
                    lp.x = __float2bfloat16(v0 - __bfloat162float(h0));
                    lp.y = __float2bfloat16(v1 - __bfloat162float(h1));
                    *(__nv_bfloat162*)(Ohi + (size_t)grow * EMB + col) = hp;
                    *(__nv_bfloat162*)(Olo + (size_t)grow * EMB + col) = lp;
                }
            }
        }
    }
}

// ---------------- per-relation aggregation (warp per node) ----------------
// out[node] += max over incoming edges of msg[src]; on the last relation of a
// layer: relu + bf16 hi/lo split (and fp32 h for the final layer's pool).
__global__ __launch_bounds__(256) void agg_rel_kernel(
    const float* __restrict__ msg, const int* __restrict__ off,
    const int* __restrict__ csr, float* __restrict__ outbuf,
    float* __restrict__ hOut,
    __nv_bfloat16* __restrict__ h_hi, __nv_bfloat16* __restrict__ h_lo,
    int last, int write_f32)
{
    int node = blockIdx.x * 8 + (threadIdx.x >> 5);
    if (node >= N_NODES) return;
    int lane = threadIdx.x & 31;
    size_t base = (size_t)node * EMB + lane * 4;

    int s = __ldg(&off[node]);
    int e = __ldg(&off[node + 1]);

    float4 acc = *(const float4*)(outbuf + base);

    if (s < e) {
        float4 m = make_float4(-FLT_MAX, -FLT_MAX, -FLT_MAX, -FLT_MAX);
        int i = s;
        int src_next = __ldg(&csr[i]);
        while (i < e) {
            int src = src_next;
            if (i + 1 < e) src_next = __ldg(&csr[i + 1]);
            float4 v = *(const float4*)(msg + (size_t)src * EMB + lane * 4);
            m.x = fmaxf(m.x, v.x);
            m.y = fmaxf(m.y, v.y);
            m.z = fmaxf(m.z, v.z);
            m.w = fmaxf(m.w, v.w);
            i++;
        }
        acc.x += m.x; acc.y += m.y; acc.z += m.z; acc.w += m.w;
    }

    if (!last) {
        *(float4*)(outbuf + base) = acc;
        return;
    }

    acc.x = fmaxf(acc.x, 0.0f);
    acc.y = fmaxf(acc.y, 0.0f);
    acc.z = fmaxf(acc.z, 0.0f);
    acc.w = fmaxf(acc.w, 0.0f);

    if (write_f32) *(float4*)(hOut + base) = acc;

    __nv_bfloat16 h0 = __float2bfloat16(acc.x);
    __nv_bfloat16 h1 = __float2bfloat16(acc.y);
    __nv_bfloat16 h2 = __float2bfloat16(acc.z);
    __nv_bfloat16 h3 = __float2bfloat16(acc.w);
    __nv_bfloat162 hp0; hp0.x = h0; hp0.y = h1;
    __nv_bfloat162 hp1; hp1.x = h2; hp1.y = h3;
    __nv_bfloat162 lp0, lp1;
    lp0.x = __float2bfloat16(acc.x - __bfloat162float(h0));
    lp0.y = __float2bfloat16(acc.y - __bfloat162float(h1));
    lp1.x = __float2bfloat16(acc.z - __bfloat162float(h2));
    lp1.y = __float2bfloat16(acc.w - __bfloat162float(h3));
    *(__nv_bfloat162*)(h_hi + base) = hp0;
    *(__nv_bfloat162*)(h_hi + base + 2) = hp1;
    *(__nv_bfloat162*)(h_lo + base) = lp0;
    *(__nv_bfloat162*)(h_lo + base + 2) = lp1;
}

// ---------------- global add pool ----------------
__global__ __launch_bounds__(128) void pool_kernel(
    const float* __restrict__ h, const int* __restrict__ batch,
    float* __restrict__ out, int n)
{
    const int NPB = 256;
    int f = threadIdx.x;
    int n0 = blockIdx.x * NPB;
    if (n0 >= n) return;
    int nend = min(n0 + NPB, n);
    float acc = 0.0f;
    int cur = batch[n0];
    for (int i = n0; i < nend; i++) {
        int b = batch[i];
        if (b != cur) {
            atomicAdd(&out[(size_t)cur * EMB + f], acc);
            acc = 0.0f;
            cur = b;
        }
        acc += h[(size_t)i * EMB + f];
    }
    atomicAdd(&out[(size_t)cur * EMB + f], acc);
}

// ---------------- host launch ----------------
extern "C" void kernel_launch(void* const* d_in, const int* in_sizes, int n_in,
                              void* d_out, int out_size)
{
    const float* x      = (const float*)d_in[0];
    const int*   e0     = (const int*)d_in[1];
    const int*   e1     = (const int*)d_in[2];
    const int*   e2     = (const int*)d_in[3];
    const int*   e3     = (const int*)d_in[4];
    const int*   batch  = (const int*)d_in[5];
    const float* emb_w  = (const float*)d_in[6];
    const float* emb_b  = (const float*)d_in[7];
    const float* root_w = (const float*)d_in[8];
    const float* root_b = (const float*)d_in[9];
    const float* conv_w = (const float*)d_in[10];
    float* out = (float*)d_out;

    void *p_h, *p_out, *p_tmp, *p_hhi, *p_hlo, *p_xhi, *p_xlo, *p_whi, *p_wlo;
    void *p_csr, *p_deg, *p_off, *p_cur, *p_bsum;
    cudaGetSymbolAddress(&p_h, g_h);
    cudaGetSymbolAddress(&p_out, g_out);
    cudaGetSymbolAddress(&p_tmp, g_tmp);
    cudaGetSymbolAddress(&p_hhi, g_h_hi);
    cudaGetSymbolAddress(&p_hlo, g_h_lo);
    cudaGetSymbolAddress(&p_xhi, g_x_hi);
    cudaGetSymbolAddress(&p_xlo, g_x_lo);
    cudaGetSymbolAddress(&p_whi, g_w_hi);
    cudaGetSymbolAddress(&p_wlo, g_w_lo);
    cudaGetSymbolAddress(&p_csr, g_csr_src);
    cudaGetSymbolAddress(&p_deg, g_deg);
    cudaGetSymbolAddress(&p_off, g_off);
    cudaGetSymbolAddress(&p_cur, g_cur);
    cudaGetSymbolAddress(&p_bsum, g_bsum);
    float* h_buf   = (float*)p_h;
    float* out_buf = (float*)p_out;
    float* tmp_buf = (float*)p_tmp;
    __nv_bfloat16* h_hi = (__nv_bfloat16*)p_hhi;
    __nv_bfloat16* h_lo = (__nv_bfloat16*)p_hlo;
    __nv_bfloat16* x_hi = (__nv_bfloat16*)p_xhi;
    __nv_bfloat16* x_lo = (__nv_bfloat16*)p_xlo;
    __nv_bfloat16* w_hi = (__nv_bfloat16*)p_whi;
    __nv_bfloat16* w_lo = (__nv_bfloat16*)p_wlo;
    int* csr = (int*)p_csr;
    int* deg = (int*)p_deg;
    int* off = (int*)p_off;
    int* cur = (int*)p_cur;
    int* bsum = (int*)p_bsum;

    // persistent side stream + events (created once; resources only, no device mem)
    static cudaStream_t s2 = []() {
        cudaStream_t s;
        cudaStreamCreateWithFlags(&s, cudaStreamNonBlocking);
        return s;
    }();
    static cudaEvent_t evFork = []() {
        cudaEvent_t e; cudaEventCreateWithFlags(&e, cudaEventDisableTiming); return e;
    }();
    static cudaEvent_t evG[N_REL] = {
        []() { cudaEvent_t e; cudaEventCreateWithFlags(&e, cudaEventDisableTiming); return e; }(),
        []() { cudaEvent_t e; cudaEventCreateWithFlags(&e, cudaEventDisableTiming); return e; }(),
        []() { cudaEvent_t e; cudaEventCreateWithFlags(&e, cudaEventDisableTiming); return e; }(),
        []() { cudaEvent_t e; cudaEventCreateWithFlags(&e, cudaEventDisableTiming); return e; }()
    };
    static cudaEvent_t evA = []() {
        cudaEvent_t e; cudaEventCreateWithFlags(&e, cudaEventDisableTiming); return e;
    }();

    const int EB = (N_EDGES + 255) / 256;
    const int GB = (N_NODES + 127) / 128;
    const int AB = (N_NODES + 7) / 8;
    const size_t MN = (size_t)N_NODES * EMB;

    // ---- fork: CSR build on s2, concurrent with splits + embed GEMM on stream 0 ----
    cudaEventRecord(evFork, 0);
    cudaStreamWaitEvent(s2, evFork, 0);

    zero_int_kernel<<<(N_REL * N_NODES + 255) / 256, 256, 0, s2>>>(deg, N_REL * N_NODES);
    hist_all_kernel<<<dim3(EB, N_REL), 256, 0, s2>>>(e0, e1, e2, e3, deg);
    scan_p1<<<dim3(SCAN_NB, N_REL), 256, 0, s2>>>(deg, bsum);
    scan_p2<<<1, 512, 0, s2>>>(bsum);
    scan_p3<<<dim3(SCAN_NB, N_REL), 256, 0, s2>>>(deg, bsum, off, cur);
    fill_all_kernel<<<dim3(EB, N_REL), 256, 0, s2>>>(e0, e1, e2, e3, cur, csr);
    // s2 now holds CSR; aggregations are enqueued on s2 so ordering is implicit.

    split_w_kernel<<<(21 * 128 * 128 + 255) / 256, 256>>>(emb_w, root_w, conv_w, w_hi, w_lo);
    split_x_kernel<<<(N_NODES * IN_FEAT + 255) / 256, 256>>>(x, x_hi, x_lo, N_NODES * IN_FEAT);
    // embed: h = x @ emb_w + emb_b -> bf16 hi/lo
    gemm_mma<<<GB, 256>>>(x_hi, x_lo, N_NODES, IN_FEAT,
                          w_hi, w_lo, emb_b, (float*)0, h_hi, h_lo);

    // ---- layers: GEMMs on stream 0, aggregations pipelined on s2 ----
    for (int l = 0; l < N_LAYERS; l++) {
        // root: out = h @ root_w[l] + root_b[l]
        gemm_mma<<<GB, 256>>>(h_hi, h_lo, N_NODES, EMB,
                              w_hi + (size_t)(1 + l) * 16384,
                              w_lo + (size_t)(1 + l) * 16384,
                              root_b + (size_t)l * EMB,
                              out_buf, (__nv_bfloat16*)0, (__nv_bfloat16*)0);
        for (int r = 0; r < N_REL; r++) {
            int slot = 5 + l * N_REL + r;
            gemm_mma<<<GB, 256>>>(h_hi, h_lo, N_NODES, EMB,
                                  w_hi + (size_t)slot * 16384,
                                  w_lo + (size_t)slot * 16384,
                                  (const float*)0,
                                  tmp_buf + (size_t)r * MN,
                                  (__nv_bfloat16*)0, (__nv_bfloat16*)0);
            cudaEventRecord(evG[r], 0);
        }
        for (int r = 0; r < N_REL; r++) {
            cudaStreamWaitEvent(s2, evG[r], 0);
            agg_rel_kernel<<<AB, 256, 0, s2>>>(
                tmp_buf + (size_t)r * MN,
                off + (size_t)r * (N_NODES + 1),
                csr + (size_t)r * N_EDGES,
                out_buf, h_buf, h_hi, h_lo,
                (r == N_REL - 1) ? 1 : 0,
                (l == N_LAYERS - 1) ? 1 : 0);
        }
        cudaEventRecord(evA, s2);
        cudaStreamWaitEvent(0, evA, 0);   // join before next layer / pool
    }

    // ---- global add pool (stream 0, after join) ----
    zero_float_kernel<<<(N_GRAPHS * EMB + 255) / 256, 256>>>(out, N_GRAPHS * EMB);
    pool_kernel<<<(N_NODES + 255) / 256, 128>>>(h_buf, batch, out, N_NODES);
}

// round 8
// speedup vs baseline: 1.2445x; 1.2445x over previous
#include <cuda_runtime.h>
#include <cuda_bf16.h>
#include <cstdint>
#include <cfloat>

#define N_NODES 100000
#define N_EDGES 500000
#define N_REL 4
#define N_LAYERS 4
#define IN_FEAT 64
#define EMB 128
#define N_GRAPHS 64
#define SCAN_NB 98   // ceil(100000/1024)

// ---------------- scratch (device globals; no allocation allowed) ----------------
__device__ float g_h[(size_t)N_NODES * EMB];     // final-layer h (for pool)
__device__ float g_out[(size_t)N_NODES * EMB];   // layer accumulator
__device__ float g_tmp[(size_t)N_NODES * EMB];   // SINGLE reused conv output (L2-hot)
__device__ __nv_bfloat16 g_h_hi[(size_t)N_NODES * EMB];
__device__ __nv_bfloat16 g_h_lo[(size_t)N_NODES * EMB];
__device__ __nv_bfloat16 g_x_hi[(size_t)N_NODES * IN_FEAT];
__device__ __nv_bfloat16 g_x_lo[(size_t)N_NODES * IN_FEAT];
// 21 weight matrices, transposed [N=128][K=128] bf16 (k contiguous):
// slot 0 = emb (K rows 64..127 zero), 1..4 = root, 5..20 = conv (l*4+r)
__device__ __nv_bfloat16 g_w_hi[(size_t)21 * 128 * 128];
__device__ __nv_bfloat16 g_w_lo[(size_t)21 * 128 * 128];
__device__ int   g_csr_src[(size_t)N_REL * N_EDGES];
__device__ int   g_deg[(size_t)N_REL * N_NODES];
__device__ int   g_off[(size_t)N_REL * (N_NODES + 1)];
__device__ int   g_cur[(size_t)N_REL * N_NODES];
__device__ int   g_bsum[(size_t)N_REL * 128];

// ---------------- warp-mma helpers (baseline PTX; valid at compute_103) ----------------
__device__ __forceinline__ uint32_t smem_u32(const void* p) {
    uint32_t a;
    asm("{ .reg .u64 t; cvta.to.shared.u64 t, %1; cvt.u32.u64 %0, t; }" : "=r"(a) : "l"(p));
    return a;
}
__device__ __forceinline__ void ldsm4(uint32_t& r0, uint32_t& r1, uint32_t& r2, uint32_t& r3,
                                      uint32_t addr) {
    asm volatile("ldmatrix.sync.aligned.m8n8.x4.shared.b16 {%0,%1,%2,%3}, [%4];"
                 : "=r"(r0), "=r"(r1), "=r"(r2), "=r"(r3) : "r"(addr));
}
__device__ __forceinline__ void mma16816(float* d, const uint32_t* a, const uint32_t* b) {
    asm volatile(
        "mma.sync.aligned.m16n8k16.row.col.f32.bf16.bf16.f32 "
        "{%0,%1,%2,%3}, {%4,%5,%6,%7}, {%8,%9}, {%0,%1,%2,%3};"
        : "+f"(d[0]), "+f"(d[1]), "+f"(d[2]), "+f"(d[3])
        : "r"(a[0]), "r"(a[1]), "r"(a[2]), "r"(a[3]), "r"(b[0]), "r"(b[1]));
}

// ---------------- utility kernels ----------------
__global__ void zero_int_kernel(int* p, int n) {
    int i = blockIdx.x * blockDim.x + threadIdx.x;
    if (i < n) p[i] = 0;
}
__global__ void zero_float_kernel(float* p, int n) {
    int i = blockIdx.x * blockDim.x + threadIdx.x;
    if (i < n) p[i] = 0.0f;
}

__global__ void hist_all_kernel(const int* __restrict__ e0, const int* __restrict__ e1,
                                const int* __restrict__ e2, const int* __restrict__ e3,
                                int* __restrict__ deg) {
    int r = blockIdx.y;
    const int* dst = ((r == 0) ? e0 : (r == 1) ? e1 : (r == 2) ? e2 : e3) + N_EDGES;
    int i = blockIdx.x * 256 + threadIdx.x;
    if (i < N_EDGES) atomicAdd(&deg[(size_t)r * N_NODES + dst[i]], 1);
}

// -------- 3-phase parallel exclusive scan of deg -> off (all relations) --------
__global__ void scan_p1(const int* __restrict__ deg, int* __restrict__ bsum) {
    int r = blockIdx.y, b = blockIdx.x, t = threadIdx.x;
    const int* d = deg + (size_t)r * N_NODES;
    int base = b * 1024 + t * 4;
    int s = 0;
#pragma unroll
    for (int j = 0; j < 4; j++) {
        int idx = base + j;
        if (idx < N_NODES) s += d[idx];
    }
    __shared__ int sm[256];
    sm[t] = s;
    __syncthreads();
    for (int o = 128; o > 0; o >>= 1) {
        if (t < o) sm[t] += sm[t + o];
        __syncthreads();
    }
    if (t == 0) bsum[r * 128 + b] = sm[0];
}
__global__ void scan_p2(int* __restrict__ bsum) {
    __shared__ int sm[512];
    int t = threadIdx.x;
    int r = t >> 7;
    int i = t & 127;
    int v = (i < SCAN_NB) ? bsum[r * 128 + i] : 0;
    sm[t] = v;
    __syncthreads();
    for (int d = 1; d < 128; d <<= 1) {
        int add = (i >= d) ? sm[t - d] : 0;
        __syncthreads();
        sm[t] += add;
        __syncthreads();
    }
    int excl = (i == 0) ? 0 : sm[t - 1];
    if (i < SCAN_NB) bsum[r * 128 + i] = excl;
}
__global__ void scan_p3(const int* __restrict__ deg, const int* __restrict__ bsum,
                        int* __restrict__ off, int* __restrict__ cur) {
    int r = blockIdx.y, b = blockIdx.x, t = threadIdx.x;
    const int* d = deg + (size_t)r * N_NODES;
    int* o = off + (size_t)r * (N_NODES + 1);
    int* c = cur + (size_t)r * N_NODES;
    int base = b * 1024 + t * 4;
    int v[4], pre[4];
    int s = 0;
#pragma unroll
    for (int j = 0; j < 4; j++) {
        int idx = base + j;
        v[j] = (idx < N_NODES) ? d[idx] : 0;
        pre[j] = s;
        s += v[j];
    }
    __shared__ int sm[256];
    sm[t] = s;
    __syncthreads();
    for (int dd = 1; dd < 256; dd <<= 1) {
        int add = (t >= dd) ? sm[t - dd] : 0;
        __syncthreads();
        sm[t] += add;
        __syncthreads();
    }
    int texcl = (t == 0) ? 0 : sm[t - 1];
    int boff = bsum[r * 128 + b];
#pragma unroll
    for (int j = 0; j < 4; j++) {
        int idx = base + j;
        if (idx < N_NODES) {
            int val = boff + texcl + pre[j];
            o[idx] = val;
            c[idx] = val;
        }
    }
    if (b == SCAN_NB - 1 && t == 255) o[N_NODES] = boff + sm[255];
}

__global__ void fill_all_kernel(const int* __restrict__ e0, const int* __restrict__ e1,
                                const int* __restrict__ e2, const int* __restrict__ e3,
                                int* __restrict__ cur, int* __restrict__ csr) {
    int r = blockIdx.y;
    const int* eptr = (r == 0) ? e0 : (r == 1) ? e1 : (r == 2) ? e2 : e3;
    int i = blockIdx.x * 256 + threadIdx.x;
    if (i < N_EDGES) {
        int dnode = eptr[N_EDGES + i];
        int pos = atomicAdd(&cur[(size_t)r * N_NODES + dnode], 1);
        csr[(size_t)r * N_EDGES + pos] = eptr[i];
    }
}

// ---------------- fp32 -> bf16 hi/lo split kernels ----------------
__global__ void split_x_kernel(const float* __restrict__ x,
                               __nv_bfloat16* __restrict__ hi,
                               __nv_bfloat16* __restrict__ lo, int n) {
    int i = blockIdx.x * blockDim.x + threadIdx.x;
    if (i >= n) return;
    float v = x[i];
    __nv_bfloat16 h = __float2bfloat16(v);
    hi[i] = h;
    lo[i] = __float2bfloat16(v - __bfloat162float(h));
}
__global__ void split_w_kernel(const float* __restrict__ emb_w,
                               const float* __restrict__ root_w,
                               const float* __restrict__ conv_w,
                               __nv_bfloat16* __restrict__ whi,
                               __nv_bfloat16* __restrict__ wlo) {
    int idx = blockIdx.x * blockDim.x + threadIdx.x;
    if (idx >= 21 * 128 * 128) return;
    int s = idx >> 14;
    int rem = idx & 16383;
    int n = rem >> 7;
    int k = rem & 127;
    float v;
    if (s == 0)      v = (k < IN_FEAT) ? emb_w[(size_t)k * EMB + n] : 0.0f;
    else if (s <= 4) v = root_w[((size_t)(s - 1) * EMB + k) * EMB + n];
    else             v = conv_w[((size_t)(s - 5) * EMB + k) * EMB + n];
    __nv_bfloat16 h = __float2bfloat16(v);
    whi[idx] = h;
    wlo[idx] = __float2bfloat16(v - __bfloat162float(h));
}

// ---------------- bf16x3 mma.sync GEMM: C[M,128] = A[M,K] @ W^T + bias ----------------
// hi+lo tiles loaded once per k-chunk; 3 emulation passes read smem.
#define BK 32
#define SSTR 40

__global__ __launch_bounds__(256, 2) void gemm_mma(
    const __nv_bfloat16* __restrict__ Ahi, const __nv_bfloat16* __restrict__ Alo,
    int M, int K,
    const __nv_bfloat16* __restrict__ Whi, const __nv_bfloat16* __restrict__ Wlo,
    const float* __restrict__ bias,
    float* __restrict__ C,
    __nv_bfloat16* __restrict__ Ohi, __nv_bfloat16* __restrict__ Olo)
{
    __shared__ __nv_bfloat16 As[2][128 * SSTR];   // [0]=hi [1]=lo
    __shared__ __nv_bfloat16 Bs[2][128 * SSTR];

    int tid = threadIdx.x;
    int wid = tid >> 5;
    int lane = tid & 31;
    int wm = wid & 1;
    int wn = wid >> 1;
    int r0 = blockIdx.x * 128;

    uint32_t as_b[2] = { smem_u32(As[0]), smem_u32(As[1]) };
    uint32_t bs_b[2] = { smem_u32(Bs[0]), smem_u32(Bs[1]) };

    float acc[4][4][4];
#pragma unroll
    for (int i = 0; i < 4; i++)
#pragma unroll
        for (int j = 0; j < 4; j++)
#pragma unroll
            for (int q = 0; q < 4; q++) acc[i][j][q] = 0.0f;

    int l_within = lane & 7;
    int l_sel = lane >> 3;

    for (int k0 = 0; k0 < K; k0 += BK) {
        __syncthreads();
        // A hi+lo tiles: 128 rows x 32 cols bf16 -> 512 x 16B each, 2 per thread
#pragma unroll
        for (int i = 0; i < 2; i++) {
            int idx = tid * 2 + i;
            int row = idx >> 2;
            int ch = idx & 3;
            uint4 vh = make_uint4(0, 0, 0, 0), vl = make_uint4(0, 0, 0, 0);
            int gr = r0 + row;
            if (gr < M) {
                vh = *(const uint4*)(Ahi + (size_t)gr * K + k0 + ch * 8);
                vl = *(const uint4*)(Alo + (size_t)gr * K + k0 + ch * 8);
            }
            *(uint4*)(&As[0][row * SSTR + ch * 8]) = vh;
            *(uint4*)(&As[1][row * SSTR + ch * 8]) = vl;
        }
        // B hi+lo tiles (W row stride = 128 elems)
#pragma unroll
        for (int i = 0; i < 2; i++) {
            int idx = tid * 2 + i;
            int row = idx >> 2;
            int ch = idx & 3;
            uint4 vh = *(const uint4*)(Whi + (size_t)row * 128 + k0 + ch * 8);
            uint4 vl = *(const uint4*)(Wlo + (size_t)row * 128 + k0 + ch * 8);
            *(uint4*)(&Bs[0][row * SSTR + ch * 8]) = vh;
            *(uint4*)(&Bs[1][row * SSTR + ch * 8]) = vl;
        }
        __syncthreads();

#pragma unroll
        for (int pass = 0; pass < 3; pass++) {
            uint32_t a_base = as_b[(pass == 2) ? 1 : 0];
            uint32_t b_base = bs_b[(pass == 1) ? 1 : 0];
#pragma unroll
            for (int ks = 0; ks < 2; ks++) {
                uint32_t af[4][4];
                uint32_t bf[4][2];
#pragma unroll
                for (int fm = 0; fm < 4; fm++) {
                    int arow = wm * 64 + fm * 16 + (l_sel & 1) * 8 + l_within;
                    int acol = ks * 16 + (l_sel >> 1) * 8;
                    ldsm4(af[fm][0], af[fm][1], af[fm][2], af[fm][3],
                          a_base + (uint32_t)(arow * SSTR + acol) * 2u);
                }
#pragma unroll
                for (int g = 0; g < 2; g++) {
                    int brow = wn * 32 + g * 16 + (l_sel >> 1) * 8 + l_within;
                    int bcol = ks * 16 + (l_sel & 1) * 8;
                    uint32_t r0v, r1v, r2v, r3v;
                    ldsm4(r0v, r1v, r2v, r3v,
                          b_base + (uint32_t)(brow * SSTR + bcol) * 2u);
                    bf[2 * g + 0][0] = r0v; bf[2 * g + 0][1] = r1v;
                    bf[2 * g + 1][0] = r2v; bf[2 * g + 1][1] = r3v;
                }
#pragma unroll
                for (int fm = 0; fm < 4; fm++)
#pragma unroll
                    for (int fn = 0; fn < 4; fn++)
                        mma16816(acc[fm][fn], af[fm], bf[fn]);
            }
        }
    }

    int qrow = lane >> 2;
    int qcol = (lane & 3) * 2;
#pragma unroll
    for (int fm = 0; fm < 4; fm++) {
#pragma unroll
        for (int half = 0; half < 2; half++) {
            int grow = r0 + wm * 64 + fm * 16 + qrow + half * 8;
            if (grow >= M) continue;
#pragma unroll
            for (int fn = 0; fn < 4; fn++) {
                int col = wn * 32 + fn * 8 + qcol;
                float v0 = acc[fm][fn][half * 2 + 0];
                float v1 = acc[fm][fn][half * 2 + 1];
                if (bias) {
                    v0 += __ldg(&bias[col]);
                    v1 += __ldg(&bias[col + 1]);
                }
                if (C) {
                    float2 fv; fv.x = v0; fv.y = v1;
                    *(float2*)(C + (size_t)grow * EMB + col) = fv;
                }
                if (Ohi) {
                    __nv_bfloat16 h0 = __float2bfloat16(v0);
                    __nv_bfloat16 h1 = __float2bfloat16(v1);
                    __nv_bfloat162 hp; hp.x = h0; hp.y = h1;
                    __nv_bfloat162 lp;
                    lp.x = __float2bfloat16(v0 - __bfloat162float(h0));
                    lp.y = __float2bfloat16(v1 - __bfloat162float(h1));
                    *(__nv_bfloat162*)(Ohi + (size_t)grow * EMB + col) = hp;
                    *(__nv_bfloat162*)(Olo + (size_t)grow * EMB + col) = lp;
                }
            }
        }
    }
}

// ---------------- per-relation aggregation (warp per node, 2-way unrolled) ----------------
__global__ __launch_bounds__(256) void agg_rel_kernel(
    const float* __restrict__ msg, const int* __restrict__ off,
    const int* __restrict__ csr, float* __restrict__ outbuf,
    float* __restrict__ hOut,
    __nv_bfloat16* __restrict__ h_hi, __nv_bfloat16* __restrict__ h_lo,
    int last, int write_f32)
{
    int node = blockIdx.x * 8 + (threadIdx.x >> 5);
    if (node >= N_NODES) return;
    int lane = threadIdx.x & 31;
    size_t base = (size_t)node * EMB + lane * 4;

    int s = __ldg(&off[node]);
    int e = __ldg(&off[node + 1]);

    float4 acc = *(const float4*)(outbuf + base);

    if (s < e) {
        float4 m = make_float4(-FLT_MAX, -FLT_MAX, -FLT_MAX, -FLT_MAX);
        int i = s;
        for (; i + 1 < e; i += 2) {
            int s0 = __ldg(&csr[i]);
            int s1 = __ldg(&csr[i + 1]);
            float4 v0 = *(const float4*)(msg + (size_t)s0 * EMB + lane * 4);
            float4 v1 = *(const float4*)(msg + (size_t)s1 * EMB + lane * 4);
            m.x = fmaxf(m.x, fmaxf(v0.x, v1.x));
            m.y = fmaxf(m.y, fmaxf(v0.y, v1.y));
            m.z = fmaxf(m.z, fmaxf(v0.z, v1.z));
            m.w = fmaxf(m.w, fmaxf(v0.w, v1.w));
        }
        if (i < e) {
            int s0 = __ldg(&csr[i]);
            float4 v0 = *(const float4*)(msg + (size_t)s0 * EMB + lane * 4);
            m.x = fmaxf(m.x, v0.x);
            m.y = fmaxf(m.y, v0.y);
            m.z = fmaxf(m.z, v0.z);
            m.w = fmaxf(m.w, v0.w);
        }
        acc.x += m.x; acc.y += m.y; acc.z += m.z; acc.w += m.w;
    }

    if (!last) {
        *(float4*)(outbuf + base) = acc;
        return;
    }

    acc.x = fmaxf(acc.x, 0.0f);
    acc.y = fmaxf(acc.y, 0.0f);
    acc.z = fmaxf(acc.z, 0.0f);
    acc.w = fmaxf(acc.w, 0.0f);

    if (write_f32) *(float4*)(hOut + base) = acc;

    __nv_bfloat16 h0 = __float2bfloat16(acc.x);
    __nv_bfloat16 h1 = __float2bfloat16(acc.y);
    __nv_bfloat16 h2 = __float2bfloat16(acc.z);
    __nv_bfloat16 h3 = __float2bfloat16(acc.w);
    __nv_bfloat162 hp0; hp0.x = h0; hp0.y = h1;
    __nv_bfloat162 hp1; hp1.x = h2; hp1.y = h3;
    __nv_bfloat162 lp0, lp1;
    lp0.x = __float2bfloat16(acc.x - __bfloat162float(h0));
    lp0.y = __float2bfloat16(acc.y - __bfloat162float(h1));
    lp1.x = __float2bfloat16(acc.z - __bfloat162float(h2));
    lp1.y = __float2bfloat16(acc.w - __bfloat162float(h3));
    *(__nv_bfloat162*)(h_hi + base) = hp0;
    *(__nv_bfloat162*)(h_hi + base + 2) = hp1;
    *(__nv_bfloat162*)(h_lo + base) = lp0;
    *(__nv_bfloat162*)(h_lo + base + 2) = lp1;
}

// ---------------- global add pool ----------------
__global__ __launch_bounds__(128) void pool_kernel(
    const float* __restrict__ h, const int* __restrict__ batch,
    float* __restrict__ out, int n)
{
    const int NPB = 256;
    int f = threadIdx.x;
    int n0 = blockIdx.x * NPB;
    if (n0 >= n) return;
    int nend = min(n0 + NPB, n);
    float acc = 0.0f;
    int cur = batch[n0];
    for (int i = n0; i < nend; i++) {
        int b = batch[i];
        if (b != cur) {
            atomicAdd(&out[(size_t)cur * EMB + f], acc);
            acc = 0.0f;
            cur = b;
        }
        acc += h[(size_t)i * EMB + f];
    }
    atomicAdd(&out[(size_t)cur * EMB + f], acc);
}

// ---------------- host launch ----------------
extern "C" void kernel_launch(void* const* d_in, const int* in_sizes, int n_in,
                              void* d_out, int out_size)
{
    const float* x      = (const float*)d_in[0];
    const int*   e0     = (const int*)d_in[1];
    const int*   e1     = (const int*)d_in[2];
    const int*   e2     = (const int*)d_in[3];
    const int*   e3     = (const int*)d_in[4];
    const int*   batch  = (const int*)d_in[5];
    const float* emb_w  = (const float*)d_in[6];
    const float* emb_b  = (const float*)d_in[7];
    const float* root_w = (const float*)d_in[8];
    const float* root_b = (const float*)d_in[9];
    const float* conv_w = (const float*)d_in[10];
    float* out = (float*)d_out;

    void *p_h, *p_out, *p_tmp, *p_hhi, *p_hlo, *p_xhi, *p_xlo, *p_whi, *p_wlo;
    void *p_csr, *p_deg, *p_off, *p_cur, *p_bsum;
    cudaGetSymbolAddress(&p_h, g_h);
    cudaGetSymbolAddress(&p_out, g_out);
    cudaGetSymbolAddress(&p_tmp, g_tmp);
    cudaGetSymbolAddress(&p_hhi, g_h_hi);
    cudaGetSymbolAddress(&p_hlo, g_h_lo);
    cudaGetSymbolAddress(&p_xhi, g_x_hi);
    cudaGetSymbolAddress(&p_xlo, g_x_lo);
    cudaGetSymbolAddress(&p_whi, g_w_hi);
    cudaGetSymbolAddress(&p_wlo, g_w_lo);
    cudaGetSymbolAddress(&p_csr, g_csr_src);
    cudaGetSymbolAddress(&p_deg, g_deg);
    cudaGetSymbolAddress(&p_off, g_off);
    cudaGetSymbolAddress(&p_cur, g_cur);
    cudaGetSymbolAddress(&p_bsum, g_bsum);
    float* h_buf   = (float*)p_h;
    float* out_buf = (float*)p_out;
    float* tmp_buf = (float*)p_tmp;
    __nv_bfloat16* h_hi = (__nv_bfloat16*)p_hhi;
    __nv_bfloat16* h_lo = (__nv_bfloat16*)p_hlo;
    __nv_bfloat16* x_hi = (__nv_bfloat16*)p_xhi;
    __nv_bfloat16* x_lo = (__nv_bfloat16*)p_xlo;
    __nv_bfloat16* w_hi = (__nv_bfloat16*)p_whi;
    __nv_bfloat16* w_lo = (__nv_bfloat16*)p_wlo;
    int* csr = (int*)p_csr;
    int* deg = (int*)p_deg;
    int* off = (int*)p_off;
    int* cur = (int*)p_cur;
    int* bsum = (int*)p_bsum;

    // side stream for CSR build only (overlaps with splits + embed GEMM)
    static cudaStream_t s2 = []() {
        cudaStream_t s;
        cudaStreamCreateWithFlags(&s, cudaStreamNonBlocking);
        return s;
    }();
    static cudaEvent_t evFork = []() {
        cudaEvent_t e; cudaEventCreateWithFlags(&e, cudaEventDisableTiming); return e;
    }();
    static cudaEvent_t evCsr = []() {
        cudaEvent_t e; cudaEventCreateWithFlags(&e, cudaEventDisableTiming); return e;
    }();

    const int EB = (N_EDGES + 255) / 256;
    const int GB = (N_NODES + 127) / 128;
    const int AB = (N_NODES + 7) / 8;

    // ---- fork CSR build to s2 ----
    cudaEventRecord(evFork, 0);
    cudaStreamWaitEvent(s2, evFork, 0);
    zero_int_kernel<<<(N_REL * N_NODES + 255) / 256, 256, 0, s2>>>(deg, N_REL * N_NODES);
    hist_all_kernel<<<dim3(EB, N_REL), 256, 0, s2>>>(e0, e1, e2, e3, deg);
    scan_p1<<<dim3(SCAN_NB, N_REL), 256, 0, s2>>>(deg, bsum);
    scan_p2<<<1, 512, 0, s2>>>(bsum);
    scan_p3<<<dim3(SCAN_NB, N_REL), 256, 0, s2>>>(deg, bsum, off, cur);
    fill_all_kernel<<<dim3(EB, N_REL), 256, 0, s2>>>(e0, e1, e2, e3, cur, csr);
    cudaEventRecord(evCsr, s2);

    // ---- main stream: splits + embed ----
    split_w_kernel<<<(21 * 128 * 128 + 255) / 256, 256>>>(emb_w, root_w, conv_w, w_hi, w_lo);
    split_x_kernel<<<(N_NODES * IN_FEAT + 255) / 256, 256>>>(x, x_hi, x_lo, N_NODES * IN_FEAT);
    gemm_mma<<<GB, 256>>>(x_hi, x_lo, N_NODES, IN_FEAT,
                          w_hi, w_lo, emb_b, (float*)0, h_hi, h_lo);

    bool joined = false;
    for (int l = 0; l < N_LAYERS; l++) {
        // root: out = h @ root_w[l] + root_b[l]
        gemm_mma<<<GB, 256>>>(h_hi, h_lo, N_NODES, EMB,
                              w_hi + (size_t)(1 + l) * 16384,
                              w_lo + (size_t)(1 + l) * 16384,
                              root_b + (size_t)l * EMB,
                              out_buf, (__nv_bfloat16*)0, (__nv_bfloat16*)0);
        for (int r = 0; r < N_REL; r++) {
            int slot = 5 + l * N_REL + r;
            // conv GEMM writes the single L2-hot tmp buffer
            gemm_mma<<<GB, 256>>>(h_hi, h_lo, N_NODES, EMB,
                                  w_hi + (size_t)slot * 16384,
                                  w_lo + (size_t)slot * 16384,
                                  (const float*)0, tmp_buf,
                                  (__nv_bfloat16*)0, (__nv_bfloat16*)0);
            if (!joined) {
                cudaStreamWaitEvent(0, evCsr, 0);   // CSR ready before first agg
                joined = true;
            }
            // serial agg: reads tmp while it is still L2-resident
            agg_rel_kernel<<<AB, 256>>>(
                tmp_buf, off + (size_t)r * (N_NODES + 1),
                csr + (size_t)r * N_EDGES,
                out_buf, h_buf, h_hi, h_lo,
                (r == N_REL - 1) ? 1 : 0,
                (l == N_LAYERS - 1) ? 1 : 0);
        }
    }

    // ---- global add pool ----
    zero_float_kernel<<<(N_GRAPHS * EMB + 255) / 256, 256>>>(out, N_GRAPHS * EMB);
    pool_kernel<<<(N_NODES + 255) / 256, 128>>>(h_buf, batch, out, N_NODES);
}

// round 9
// speedup vs baseline: 1.3072x; 1.0504x over previous
#include <cuda_runtime.h>
#include <cuda_bf16.h>
#include <cstdint>
#include <cfloat>

#define N_NODES 100000
#define N_EDGES 500000
#define N_REL 4
#define N_LAYERS 4
#define IN_FEAT 64
#define EMB 128
#define N_GRAPHS 64
#define SCAN_NB 98   // ceil(100000/1024)

// ---------------- scratch (device globals; no allocation allowed) ----------------
__device__ float g_h[(size_t)N_NODES * EMB];     // final-layer h (for pool)
__device__ float g_out[(size_t)N_NODES * EMB];   // layer accumulator
__device__ float g_tmp0[(size_t)N_NODES * EMB];  // conv outputs (reused, L2-hot)
__device__ float g_tmp1[(size_t)N_NODES * EMB];
__device__ __nv_bfloat16 g_h_hi[(size_t)N_NODES * EMB];
__device__ __nv_bfloat16 g_h_lo[(size_t)N_NODES * EMB];
__device__ __nv_bfloat16 g_x_hi[(size_t)N_NODES * IN_FEAT];
__device__ __nv_bfloat16 g_x_lo[(size_t)N_NODES * IN_FEAT];
// 21 weight matrices, transposed [N=128][K=128] bf16 (k contiguous):
// slot 0 = emb (K rows 64..127 zero), 1..4 = root, 5..20 = conv (l*4+r)
__device__ __nv_bfloat16 g_w_hi[(size_t)21 * 128 * 128];
__device__ __nv_bfloat16 g_w_lo[(size_t)21 * 128 * 128];
__device__ int   g_csr_src[(size_t)N_REL * N_EDGES];
__device__ int   g_deg[(size_t)N_REL * N_NODES];
__device__ int   g_off[(size_t)N_REL * (N_NODES + 1)];
__device__ int   g_cur[(size_t)N_REL * N_NODES];
__device__ int   g_bsum[(size_t)N_REL * 128];

// ---------------- helpers ----------------
__device__ __forceinline__ uint32_t smem_u32(const void* p) {
    uint32_t a;
    asm("{ .reg .u64 t; cvta.to.shared.u64 t, %1; cvt.u32.u64 %0, t; }" : "=r"(a) : "l"(p));
    return a;
}
__device__ __forceinline__ void ldsm4(uint32_t& r0, uint32_t& r1, uint32_t& r2, uint32_t& r3,
                                      uint32_t addr) {
    asm volatile("ldmatrix.sync.aligned.m8n8.x4.shared.b16 {%0,%1,%2,%3}, [%4];"
                 : "=r"(r0), "=r"(r1), "=r"(r2), "=r"(r3) : "r"(addr));
}
__device__ __forceinline__ void mma16816(float* d, const uint32_t* a, const uint32_t* b) {
    asm volatile(
        "mma.sync.aligned.m16n8k16.row.col.f32.bf16.bf16.f32 "
        "{%0,%1,%2,%3}, {%4,%5,%6,%7}, {%8,%9}, {%0,%1,%2,%3};"
        : "+f"(d[0]), "+f"(d[1]), "+f"(d[2]), "+f"(d[3])
        : "r"(a[0]), "r"(a[1]), "r"(a[2]), "r"(a[3]), "r"(b[0]), "r"(b[1]));
}
#define CP_ASYNC16(dst, src, n) \
    asm volatile("cp.async.ca.shared.global [%0], [%1], 16, %2;" \
                 :: "r"(dst), "l"(src), "r"(n))

// ---------------- utility kernels ----------------
__global__ void zero_int_kernel(int* p, int n) {
    int i = blockIdx.x * blockDim.x + threadIdx.x;
    if (i < n) p[i] = 0;
}
__global__ void zero_float_kernel(float* p, int n) {
    int i = blockIdx.x * blockDim.x + threadIdx.x;
    if (i < n) p[i] = 0.0f;
}

__global__ void hist_all_kernel(const int* __restrict__ e0, const int* __restrict__ e1,
                                const int* __restrict__ e2, const int* __restrict__ e3,
                                int* __restrict__ deg) {
    int r = blockIdx.y;
    const int* dst = ((r == 0) ? e0 : (r == 1) ? e1 : (r == 2) ? e2 : e3) + N_EDGES;
    int i = blockIdx.x * 256 + threadIdx.x;
    if (i < N_EDGES) atomicAdd(&deg[(size_t)r * N_NODES + dst[i]], 1);
}

// -------- 3-phase parallel exclusive scan of deg -> off (all relations) --------
__global__ void scan_p1(const int* __restrict__ deg, int* __restrict__ bsum) {
    int r = blockIdx.y, b = blockIdx.x, t = threadIdx.x;
    const int* d = deg + (size_t)r * N_NODES;
    int base = b * 1024 + t * 4;
    int s = 0;
#pragma unroll
    for (int j = 0; j < 4; j++) {
        int idx = base + j;
        if (idx < N_NODES) s += d[idx];
    }
    __shared__ int sm[256];
    sm[t] = s;
    __syncthreads();
    for (int o = 128; o > 0; o >>= 1) {
        if (t < o) sm[t] += sm[t + o];
        __syncthreads();
    }
    if (t == 0) bsum[r * 128 + b] = sm[0];
}
__global__ void scan_p2(int* __restrict__ bsum) {
    __shared__ int sm[512];
    int t = threadIdx.x;
    int r = t >> 7;
    int i = t & 127;
    int v = (i < SCAN_NB) ? bsum[r * 128 + i] : 0;
    sm[t] = v;
    __syncthreads();
    for (int d = 1; d < 128; d <<= 1) {
        int add = (i >= d) ? sm[t - d] : 0;
        __syncthreads();
        sm[t] += add;
        __syncthreads();
    }
    int excl = (i == 0) ? 0 : sm[t - 1];
    if (i < SCAN_NB) bsum[r * 128 + i] = excl;
}
__global__ void scan_p3(const int* __restrict__ deg, const int* __restrict__ bsum,
                        int* __restrict__ off, int* __restrict__ cur) {
    int r = blockIdx.y, b = blockIdx.x, t = threadIdx.x;
    const int* d = deg + (size_t)r * N_NODES;
    int* o = off + (size_t)r * (N_NODES + 1);
    int* c = cur + (size_t)r * N_NODES;
    int base = b * 1024 + t * 4;
    int v[4], pre[4];
    int s = 0;
#pragma unroll
    for (int j = 0; j < 4; j++) {
        int idx = base + j;
        v[j] = (idx < N_NODES) ? d[idx] : 0;
        pre[j] = s;
        s += v[j];
    }
    __shared__ int sm[256];
    sm[t] = s;
    __syncthreads();
    for (int dd = 1; dd < 256; dd <<= 1) {
        int add = (t >= dd) ? sm[t - dd] : 0;
        __syncthreads();
        sm[t] += add;
        __syncthreads();
    }
    int texcl = (t == 0) ? 0 : sm[t - 1];
    int boff = bsum[r * 128 + b];
#pragma unroll
    for (int j = 0; j < 4; j++) {
        int idx = base + j;
        if (idx < N_NODES) {
            int val = boff + texcl + pre[j];
            o[idx] = val;
            c[idx] = val;
        }
    }
    if (b == SCAN_NB - 1 && t == 255) o[N_NODES] = boff + sm[255];
}

__global__ void fill_all_kernel(const int* __restrict__ e0, const int* __restrict__ e1,
                                const int* __restrict__ e2, const int* __restrict__ e3,
                                int* __restrict__ cur, int* __restrict__ csr) {
    int r = blockIdx.y;
    const int* eptr = (r == 0) ? e0 : (r == 1) ? e1 : (r == 2) ? e2 : e3;
    int i = blockIdx.x * 256 + threadIdx.x;
    if (i < N_EDGES) {
        int dnode = eptr[N_EDGES + i];
        int pos = atomicAdd(&cur[(size_t)r * N_NODES + dnode], 1);
        csr[(size_t)r * N_EDGES + pos] = eptr[i];
    }
}

// ---------------- fp32 -> bf16 hi/lo split kernels ----------------
__global__ void split_x_kernel(const float* __restrict__ x,
                               __nv_bfloat16* __restrict__ hi,
                               __nv_bfloat16* __restrict__ lo, int n) {
    int i = blockIdx.x * blockDim.x + threadIdx.x;
    if (i >= n) return;
    float v = x[i];
    __nv_bfloat16 h = __float2bfloat16(v);
    hi[i] = h;
    lo[i] = __float2bfloat16(v - __bfloat162float(h));
}
__global__ void split_w_kernel(const float* __restrict__ emb_w,
                               const float* __restrict__ root_w,
                               const float* __restrict__ conv_w,
                               __nv_bfloat16* __restrict__ whi,
                               __nv_bfloat16* __restrict__ wlo) {
    int idx = blockIdx.x * blockDim.x + threadIdx.x;
    if (idx >= 21 * 128 * 128) return;
    int s = idx >> 14;
    int rem = idx & 16383;
    int n = rem >> 7;
    int k = rem & 127;
    float v;
    if (s == 0)      v = (k < IN_FEAT) ? emb_w[(size_t)k * EMB + n] : 0.0f;
    else if (s <= 4) v = root_w[((size_t)(s - 1) * EMB + k) * EMB + n];
    else             v = conv_w[((size_t)(s - 5) * EMB + k) * EMB + n];
    __nv_bfloat16 h = __float2bfloat16(v);
    whi[idx] = h;
    wlo[idx] = __float2bfloat16(v - __bfloat162float(h));
}

// ---------------- bf16x3 mma.sync GEMM, cp.async 2-stage pipeline ----------------
// blockIdx.y selects (slot, output): y0 -> slotA/C0 (+bias/Ohi), y1 -> slotB/C1, y2 -> slotC/C2.
#define BK 32
#define SSTR 40
#define TILE_E (128 * SSTR)          // bf16 elems per tile
#define TILE_B (TILE_E * 2)          // bytes per tile
#define GEMM_SMEM (8 * TILE_B)       // 2 stages x (A hi/lo + B hi/lo) = 81920 B

__global__ __launch_bounds__(256, 2) void gemm_mma(
    const __nv_bfloat16* __restrict__ Ahi, const __nv_bfloat16* __restrict__ Alo,
    int M, int K,
    const __nv_bfloat16* __restrict__ whi_base, const __nv_bfloat16* __restrict__ wlo_base,
    int slotA, int slotB, int slotC,
    const float* __restrict__ bias0,
    float* __restrict__ C0, float* __restrict__ C1, float* __restrict__ C2,
    __nv_bfloat16* __restrict__ Ohi, __nv_bfloat16* __restrict__ Olo)
{
    extern __shared__ __nv_bfloat16 sm_dyn[];
    // layout: A tiles [stage][hi/lo], then B tiles [stage][hi/lo]
    __nv_bfloat16* As = sm_dyn;              // 4 * TILE_E
    __nv_bfloat16* Bs = sm_dyn + 4 * TILE_E; // 4 * TILE_E

    int y = blockIdx.y;
    int slot = (y == 0) ? slotA : (y == 1) ? slotB : slotC;
    const __nv_bfloat16* Whi = whi_base + (size_t)slot * 16384;
    const __nv_bfloat16* Wlo = wlo_base + (size_t)slot * 16384;
    const float* bias = (y == 0) ? bias0 : (const float*)0;
    float* C = (y == 0) ? C0 : (y == 1) ? C1 : C2;
    __nv_bfloat16* OhiL = (y == 0) ? Ohi : (__nv_bfloat16*)0;
    __nv_bfloat16* OloL = (y == 0) ? Olo : (__nv_bfloat16*)0;

    int tid = threadIdx.x;
    int wid = tid >> 5;
    int lane = tid & 31;
    int wm = wid & 1;
    int wn = wid >> 1;
    int r0 = blockIdx.x * 128;

    uint32_t as_u = smem_u32(As);
    uint32_t bs_u = smem_u32(Bs);

    float acc[4][4][4];
#pragma unroll
    for (int i = 0; i < 4; i++)
#pragma unroll
        for (int j = 0; j < 4; j++)
#pragma unroll
            for (int q = 0; q < 4; q++) acc[i][j][q] = 0.0f;

    int l_within = lane & 7;
    int l_sel = lane >> 3;
    int nch = K >> 5;

    // per-thread load coords (2 x 16B per tile kind)
    int li0 = tid * 2, li1 = tid * 2 + 1;
    int lr0 = li0 >> 2, lc0 = li0 & 3;
    int lr1 = li1 >> 2, lc1 = li1 & 3;

    auto load_stage = [&](int kc, int st) {
        int k0 = kc * BK;
#pragma unroll
        for (int i = 0; i < 2; i++) {
            int row = i ? lr1 : lr0;
            int ch  = i ? lc1 : lc0;
            int gr = r0 + row;
            int ok = (gr < M) ? 16 : 0;
            int grc = (gr < M) ? gr : 0;
            uint32_t soff = (uint32_t)(row * SSTR + ch * 8) * 2u;
            const __nv_bfloat16* pah = Ahi + (size_t)grc * K + k0 + ch * 8;
            const __nv_bfloat16* pal = Alo + (size_t)grc * K + k0 + ch * 8;
            CP_ASYNC16(as_u + (uint32_t)(st * 2 + 0) * TILE_B + soff,
                       (uint64_t)__cvta_generic_to_global(pah), ok);
            CP_ASYNC16(as_u + (uint32_t)(st * 2 + 1) * TILE_B + soff,
                       (uint64_t)__cvta_generic_to_global(pal), ok);
            const __nv_bfloat16* pbh = Whi + (size_t)row * 128 + k0 + ch * 8;
            const __nv_bfloat16* pbl = Wlo + (size_t)row * 128 + k0 + ch * 8;
            CP_ASYNC16(bs_u + (uint32_t)(st * 2 + 0) * TILE_B + soff,
                       (uint64_t)__cvta_generic_to_global(pbh), 16);
            CP_ASYNC16(bs_u + (uint32_t)(st * 2 + 1) * TILE_B + soff,
                       (uint64_t)__cvta_generic_to_global(pbl), 16);
        }
        asm volatile("cp.async.commit_group;");
    };

    load_stage(0, 0);
    for (int kc = 0; kc < nch; kc++) {
        int st = kc & 1;
        if (kc + 1 < nch) {
            load_stage(kc + 1, st ^ 1);
            asm volatile("cp.async.wait_group 1;");
        } else {
            asm volatile("cp.async.wait_group 0;");
        }
        __syncthreads();

#pragma unroll
        for (int pass = 0; pass < 3; pass++) {
            uint32_t a_base = as_u + (uint32_t)(st * 2 + ((pass == 2) ? 1 : 0)) * TILE_B;
            uint32_t b_base = bs_u + (uint32_t)(st * 2 + ((pass == 1) ? 1 : 0)) * TILE_B;
#pragma unroll
            for (int ks = 0; ks < 2; ks++) {
                uint32_t af[4][4];
                uint32_t bf[4][2];
#pragma unroll
                for (int fm = 0; fm < 4; fm++) {
                    int arow = wm * 64 + fm * 16 + (l_sel & 1) * 8 + l_within;
                    int acol = ks * 16 + (l_sel >> 1) * 8;
                    ldsm4(af[fm][0], af[fm][1], af[fm][2], af[fm][3],
                          a_base + (uint32_t)(arow * SSTR + acol) * 2u);
                }
#pragma unroll
                for (int g = 0; g < 2; g++) {
                    int brow = wn * 32 + g * 16 + (l_sel >> 1) * 8 + l_within;
                    int bcol = ks * 16 + (l_sel & 1) * 8;
                    uint32_t r0v, r1v, r2v, r3v;
                    ldsm4(r0v, r1v, r2v, r3v,
                          b_base + (uint32_t)(brow * SSTR + bcol) * 2u);
                    bf[2 * g + 0][0] = r0v; bf[2 * g + 0][1] = r1v;
                    bf[2 * g + 1][0] = r2v; bf[2 * g + 1][1] = r3v;
                }
#pragma unroll
                for (int fm = 0; fm < 4; fm++)
#pragma unroll
                    for (int fn = 0; fn < 4; fn++)
                        mma16816(acc[fm][fn], af[fm], bf[fn]);
            }
        }
        __syncthreads();
    }

    int qrow = lane >> 2;
    int qcol = (lane & 3) * 2;
#pragma unroll
    for (int fm = 0; fm < 4; fm++) {
#pragma unroll
        for (int half = 0; half < 2; half++) {
            int grow = r0 + wm * 64 + fm * 16 + qrow + half * 8;
            if (grow >= M) continue;
#pragma unroll
            for (int fn = 0; fn < 4; fn++) {
                int col = wn * 32 + fn * 8 + qcol;
                float v0 = acc[fm][fn][half * 2 + 0];
                float v1 = acc[fm][fn][half * 2 + 1];
                if (bias) {
                    v0 += __ldg(&bias[col]);
                    v1 += __ldg(&bias[col + 1]);
                }
                if (C) {
                    float2 fv; fv.x = v0; fv.y = v1;
                    *(float2*)(C + (size_t)grow * EMB + col) = fv;
                }
                if (OhiL) {
                    __nv_bfloat16 h0 = __float2bfloat16(v0);
                    __nv_bfloat16 h1 = __float2bfloat16(v1);
                    __nv_bfloat162 hp; hp.x = h0; hp.y = h1;
                    __nv_bfloat162 lp;
                    lp.x = __float2bfloat16(v0 - __bfloat162float(h0));
                    lp.y = __float2bfloat16(v1 - __bfloat162float(h1));
                    *(__nv_bfloat162*)(OhiL + (size_t)grow * EMB + col) = hp;
                    *(__nv_bfloat162*)(OloL + (size_t)grow * EMB + col) = lp;
                }
            }
        }
    }
}

// ---------------- pair-fused aggregation (warp per node) ----------------
__device__ __forceinline__ void agg_one_rel(
    const float* __restrict__ msg, const int* __restrict__ off,
    const int* __restrict__ csr, int node, int lane, float4& acc)
{
    int s = __ldg(&off[node]);
    int e = __ldg(&off[node + 1]);
    if (s >= e) return;
    float4 m = make_float4(-FLT_MAX, -FLT_MAX, -FLT_MAX, -FLT_MAX);
    int i = s;
    for (; i + 1 < e; i += 2) {
        int s0 = __ldg(&csr[i]);
        int s1 = __ldg(&csr[i + 1]);
        float4 v0 = *(const float4*)(msg + (size_t)s0 * EMB + lane * 4);
        float4 v1 = *(const float4*)(msg + (size_t)s1 * EMB + lane * 4);
        m.x = fmaxf(m.x, fmaxf(v0.x, v1.x));
        m.y = fmaxf(m.y, fmaxf(v0.y, v1.y));
        m.z = fmaxf(m.z, fmaxf(v0.z, v1.z));
        m.w = fmaxf(m.w, fmaxf(v0.w, v1.w));
    }
    if (i < e) {
        int s0 = __ldg(&csr[i]);
        float4 v0 = *(const float4*)(msg + (size_t)s0 * EMB + lane * 4);
        m.x = fmaxf(m.x, v0.x);
        m.y = fmaxf(m.y, v0.y);
        m.z = fmaxf(m.z, v0.z);
        m.w = fmaxf(m.w, v0.w);
    }
    acc.x += m.x; acc.y += m.y; acc.z += m.z; acc.w += m.w;
}

__global__ __launch_bounds__(256) void agg_pair_kernel(
    const float* __restrict__ msg0, const float* __restrict__ msg1,
    const int* __restrict__ off0, const int* __restrict__ csr0,
    const int* __restrict__ off1, const int* __restrict__ csr1,
    float* __restrict__ outbuf, float* __restrict__ hOut,
    __nv_bfloat16* __restrict__ h_hi, __nv_bfloat16* __restrict__ h_lo,
    int last, int write_f32)
{
    int node = blockIdx.x * 8 + (threadIdx.x >> 5);
    if (node >= N_NODES) return;
    int lane = threadIdx.x & 31;
    size_t base = (size_t)node * EMB + lane * 4;

    float4 acc = __ldcs((const float4*)(outbuf + base));  // streaming: don't pollute L2

    agg_one_rel(msg0, off0, csr0, node, lane, acc);
    agg_one_rel(msg1, off1, csr1, node, lane, acc);

    if (!last) {
        __stcs((float4*)(outbuf + base), acc);
        return;
    }

    acc.x = fmaxf(acc.x, 0.0f);
    acc.y = fmaxf(acc.y, 0.0f);
    acc.z = fmaxf(acc.z, 0.0f);
    acc.w = fmaxf(acc.w, 0.0f);

    if (write_f32) *(float4*)(hOut + base) = acc;

    __nv_bfloat16 h0 = __float2bfloat16(acc.x);
    __nv_bfloat16 h1 = __float2bfloat16(acc.y);
    __nv_bfloat16 h2 = __float2bfloat16(acc.z);
    __nv_bfloat16 h3 = __float2bfloat16(acc.w);
    __nv_bfloat162 hp0; hp0.x = h0; hp0.y = h1;
    __nv_bfloat162 hp1; hp1.x = h2; hp1.y = h3;
    __nv_bfloat162 lp0, lp1;
    lp0.x = __float2bfloat16(acc.x - __bfloat162float(h0));
    lp0.y = __float2bfloat16(acc.y - __bfloat162float(h1));
    lp1.x = __float2bfloat16(acc.z - __bfloat162float(h2));
    lp1.y = __float2bfloat16(acc.w - __bfloat162float(h3));
    *(__nv_bfloat162*)(h_hi + base) = hp0;
    *(__nv_bfloat162*)(h_hi + base + 2) = hp1;
    *(__nv_bfloat162*)(h_lo + base) = lp0;
    *(__nv_bfloat162*)(h_lo + base + 2) = lp1;
}

// ---------------- global add pool ----------------
__global__ __launch_bounds__(128) void pool_kernel(
    const float* __restrict__ h, const int* __restrict__ batch,
    float* __restrict__ out, int n)
{
    const int NPB = 256;
    int f = threadIdx.x;
    int n0 = blockIdx.x * NPB;
    if (n0 >= n) return;
    int nend = min(n0 + NPB, n);
    float acc = 0.0f;
    int cur = batch[n0];
    for (int i = n0; i < nend; i++) {
        int b = batch[i];
        if (b != cur) {
            atomicAdd(&out[(size_t)cur * EMB + f], acc);
            acc = 0.0f;
            cur = b;
        }
        acc += h[(size_t)i * EMB + f];
    }
    atomicAdd(&out[(size_t)cur * EMB + f], acc);
}

// ---------------- host launch ----------------
extern "C" void kernel_launch(void* const* d_in, const int* in_sizes, int n_in,
                              void* d_out, int out_size)
{
    const float* x      = (const float*)d_in[0];
    const int*   e0     = (const int*)d_in[1];
    const int*   e1     = (const int*)d_in[2];
    const int*   e2     = (const int*)d_in[3];
    const int*   e3     = (const int*)d_in[4];
    const int*   batch  = (const int*)d_in[5];
    const float* emb_w  = (const float*)d_in[6];
    const float* emb_b  = (const float*)d_in[7];
    const float* root_w = (const float*)d_in[8];
    const float* root_b = (const float*)d_in[9];
    const float* conv_w = (const float*)d_in[10];
    float* out = (float*)d_out;

    void *p_h, *p_out, *p_t0, *p_t1, *p_hhi, *p_hlo, *p_xhi, *p_xlo, *p_whi, *p_wlo;
    void *p_csr, *p_deg, *p_off, *p_cur, *p_bsum;
    cudaGetSymbolAddress(&p_h, g_h);
    cudaGetSymbolAddress(&p_out, g_out);
    cudaGetSymbolAddress(&p_t0, g_tmp0);
    cudaGetSymbolAddress(&p_t1, g_tmp1);
    cudaGetSymbolAddress(&p_hhi, g_h_hi);
    cudaGetSymbolAddress(&p_hlo, g_h_lo);
    cudaGetSymbolAddress(&p_xhi, g_x_hi);
    cudaGetSymbolAddress(&p_xlo, g_x_lo);
    cudaGetSymbolAddress(&p_whi, g_w_hi);
    cudaGetSymbolAddress(&p_wlo, g_w_lo);
    cudaGetSymbolAddress(&p_csr, g_csr_src);
    cudaGetSymbolAddress(&p_deg, g_deg);
    cudaGetSymbolAddress(&p_off, g_off);
    cudaGetSymbolAddress(&p_cur, g_cur);
    cudaGetSymbolAddress(&p_bsum, g_bsum);
    float* h_buf  = (float*)p_h;
    float* out_buf = (float*)p_out;
    float* tmp0 = (float*)p_t0;
    float* tmp1 = (float*)p_t1;
    __nv_bfloat16* h_hi = (__nv_bfloat16*)p_hhi;
    __nv_bfloat16* h_lo = (__nv_bfloat16*)p_hlo;
    __nv_bfloat16* x_hi = (__nv_bfloat16*)p_xhi;
    __nv_bfloat16* x_lo = (__nv_bfloat16*)p_xlo;
    __nv_bfloat16* w_hi = (__nv_bfloat16*)p_whi;
    __nv_bfloat16* w_lo = (__nv_bfloat16*)p_wlo;
    int* csr = (int*)p_csr;
    int* deg = (int*)p_deg;
    int* off = (int*)p_off;
    int* cur = (int*)p_cur;
    int* bsum = (int*)p_bsum;

    static bool attr_set = []() {
        cudaFuncSetAttribute(gemm_mma, cudaFuncAttributeMaxDynamicSharedMemorySize, GEMM_SMEM);
        return true;
    }();
    (void)attr_set;

    static cudaStream_t s2 = []() {
        cudaStream_t s;
        cudaStreamCreateWithFlags(&s, cudaStreamNonBlocking);
        return s;
    }();
    static cudaEvent_t evFork = []() {
        cudaEvent_t e; cudaEventCreateWithFlags(&e, cudaEventDisableTiming); return e;
    }();
    static cudaEvent_t evCsr = []() {
        cudaEvent_t e; cudaEventCreateWithFlags(&e, cudaEventDisableTiming); return e;
    }();

    const int EB = (N_EDGES + 255) / 256;
    const int GB = (N_NODES + 127) / 128;
    const int AB = (N_NODES + 7) / 8;

    // ---- fork CSR build to s2 (overlaps with splits + embed GEMM) ----
    cudaEventRecord(evFork, 0);
    cudaStreamWaitEvent(s2, evFork, 0);
    zero_int_kernel<<<(N_REL * N_NODES + 255) / 256, 256, 0, s2>>>(deg, N_REL * N_NODES);
    hist_all_kernel<<<dim3(EB, N_REL), 256, 0, s2>>>(e0, e1, e2, e3, deg);
    scan_p1<<<dim3(SCAN_NB, N_REL), 256, 0, s2>>>(deg, bsum);
    scan_p2<<<1, 512, 0, s2>>>(bsum);
    scan_p3<<<dim3(SCAN_NB, N_REL), 256, 0, s2>>>(deg, bsum, off, cur);
    fill_all_kernel<<<dim3(EB, N_REL), 256, 0, s2>>>(e0, e1, e2, e3, cur, csr);
    cudaEventRecord(evCsr, s2);

    // ---- main stream: splits + embed ----
    split_w_kernel<<<(21 * 128 * 128 + 255) / 256, 256>>>(emb_w, root_w, conv_w, w_hi, w_lo);
    split_x_kernel<<<(N_NODES * IN_FEAT + 255) / 256, 256>>>(x, x_hi, x_lo, N_NODES * IN_FEAT);
    gemm_mma<<<dim3(GB, 1), 256, GEMM_SMEM>>>(x_hi, x_lo, N_NODES, IN_FEAT, w_hi, w_lo,
                                              0, 0, 0, emb_b,
                                              (float*)0, (float*)0, (float*)0, h_hi, h_lo);

    bool joined = false;
    for (int l = 0; l < N_LAYERS; l++) {
        int cb = 5 + l * N_REL;
        // root + conv0 + conv1 (batched)
        gemm_mma<<<dim3(GB, 3), 256, GEMM_SMEM>>>(h_hi, h_lo, N_NODES, EMB, w_hi, w_lo,
                                                  1 + l, cb, cb + 1,
                                                  root_b + (size_t)l * EMB,
                                                  out_buf, tmp0, tmp1,
                                                  (__nv_bfloat16*)0, (__nv_bfloat16*)0);
        if (!joined) {
            cudaStreamWaitEvent(0, evCsr, 0);
            joined = true;
        }
        agg_pair_kernel<<<AB, 256>>>(tmp0, tmp1,
                                     off, csr,
                                     off + (size_t)(N_NODES + 1), csr + (size_t)N_EDGES,
                                     out_buf, h_buf, h_hi, h_lo, 0, 0);
        // conv2 + conv3 (batched, reuse tmp buffers)
        gemm_mma<<<dim3(GB, 2), 256, GEMM_SMEM>>>(h_hi, h_lo, N_NODES, EMB, w_hi, w_lo,
                                                  cb + 2, cb + 3, 0,
                                                  (const float*)0,
                                                  tmp0, tmp1, (float*)0,
                                                  (__nv_bfloat16*)0, (__nv_bfloat16*)0);
        agg_pair_kernel<<<AB, 256>>>(tmp0, tmp1,
                                     off + (size_t)2 * (N_NODES + 1), csr + (size_t)2 * N_EDGES,
                                     off + (size_t)3 * (N_NODES + 1), csr + (size_t)3 * N_EDGES,
                                     out_buf, h_buf, h_hi, h_lo, 1,
                                     (l == N_LAYERS - 1) ? 1 : 0);
    }

    // ---- global add pool ----
    zero_float_kernel<<<(N_GRAPHS * EMB + 255) / 256, 256>>>(out, N_GRAPHS * EMB);
    pool_kernel<<<(N_NODES + 255) / 256, 128>>>(h_buf, batch, out, N_NODES);
}

// round 10
// speedup vs baseline: 2.0671x; 1.5813x over previous
#include <cuda_runtime.h>
#include <cuda_fp16.h>
#include <cstdint>
#include <cfloat>

#define N_NODES 100000
#define N_EDGES 500000
#define N_REL 4
#define N_LAYERS 4
#define IN_FEAT 64
#define EMB 128
#define N_GRAPHS 64
#define SCAN_NB 98   // ceil(100000/1024)

// ---------------- scratch (device globals; no allocation allowed) ----------------
__device__ float  g_h[(size_t)N_NODES * EMB];     // final-layer h fp32 (for pool)
__device__ float  g_out[(size_t)N_NODES * EMB];   // layer accumulator fp32
__device__ __half g_tmp0[(size_t)N_NODES * EMB];  // conv outputs fp16 (L2-hot)
__device__ __half g_tmp1[(size_t)N_NODES * EMB];
__device__ __half g_h16[(size_t)N_NODES * EMB];   // h fp16 (GEMM A operand)
__device__ __half g_x16[(size_t)N_NODES * IN_FEAT];
// 21 weight matrices, transposed [N=128][K=128] fp16 hi + fp16 residual:
// slot 0 = emb (K rows 64..127 zero), 1..4 = root, 5..20 = conv (l*4+r)
__device__ __half g_w_hi[(size_t)21 * 128 * 128];
__device__ __half g_w_lo[(size_t)21 * 128 * 128];
__device__ int   g_csr_src[(size_t)N_REL * N_EDGES];
__device__ int   g_deg[(size_t)N_REL * N_NODES];
__device__ int   g_off[(size_t)N_REL * (N_NODES + 1)];
__device__ int   g_cur[(size_t)N_REL * N_NODES];
__device__ int   g_bsum[(size_t)N_REL * 128];

// ---------------- helpers ----------------
__device__ __forceinline__ uint32_t smem_u32(const void* p) {
    uint32_t a;
    asm("{ .reg .u64 t; cvta.to.shared.u64 t, %1; cvt.u32.u64 %0, t; }" : "=r"(a) : "l"(p));
    return a;
}
__device__ __forceinline__ void ldsm4(uint32_t& r0, uint32_t& r1, uint32_t& r2, uint32_t& r3,
                                      uint32_t addr) {
    asm volatile("ldmatrix.sync.aligned.m8n8.x4.shared.b16 {%0,%1,%2,%3}, [%4];"
                 : "=r"(r0), "=r"(r1), "=r"(r2), "=r"(r3) : "r"(addr));
}
__device__ __forceinline__ void mma16816(float* d, const uint32_t* a, const uint32_t* b) {
    asm volatile(
        "mma.sync.aligned.m16n8k16.row.col.f32.f16.f16.f32 "
        "{%0,%1,%2,%3}, {%4,%5,%6,%7}, {%8,%9}, {%0,%1,%2,%3};"
        : "+f"(d[0]), "+f"(d[1]), "+f"(d[2]), "+f"(d[3])
        : "r"(a[0]), "r"(a[1]), "r"(a[2]), "r"(a[3]), "r"(b[0]), "r"(b[1]));
}
#define CP_ASYNC16(dst, src, n) \
    asm volatile("cp.async.ca.shared.global [%0], [%1], 16, %2;" \
                 :: "r"(dst), "l"(src), "r"(n))

// ---------------- utility kernels ----------------
__global__ void zero_int_kernel(int* p, int n) {
    int i = blockIdx.x * blockDim.x + threadIdx.x;
    if (i < n) p[i] = 0;
}
__global__ void zero_float_kernel(float* p, int n) {
    int i = blockIdx.x * blockDim.x + threadIdx.x;
    if (i < n) p[i] = 0.0f;
}

__global__ void hist_all_kernel(const int* __restrict__ e0, const int* __restrict__ e1,
                                const int* __restrict__ e2, const int* __restrict__ e3,
                                int* __restrict__ deg) {
    int r = blockIdx.y;
    const int* dst = ((r == 0) ? e0 : (r == 1) ? e1 : (r == 2) ? e2 : e3) + N_EDGES;
    int i = blockIdx.x * 256 + threadIdx.x;
    if (i < N_EDGES) atomicAdd(&deg[(size_t)r * N_NODES + dst[i]], 1);
}

// -------- 3-phase parallel exclusive scan of deg -> off (all relations) --------
__global__ void scan_p1(const int* __restrict__ deg, int* __restrict__ bsum) {
    int r = blockIdx.y, b = blockIdx.x, t = threadIdx.x;
    const int* d = deg + (size_t)r * N_NODES;
    int base = b * 1024 + t * 4;
    int s = 0;
#pragma unroll
    for (int j = 0; j < 4; j++) {
        int idx = base + j;
        if (idx < N_NODES) s += d[idx];
    }
    __shared__ int sm[256];
    sm[t] = s;
    __syncthreads();
    for (int o = 128; o > 0; o >>= 1) {
        if (t < o) sm[t] += sm[t + o];
        __syncthreads();
    }
    if (t == 0) bsum[r * 128 + b] = sm[0];
}
__global__ void scan_p2(int* __restrict__ bsum) {
    __shared__ int sm[512];
    int t = threadIdx.x;
    int r = t >> 7;
    int i = t & 127;
    int v = (i < SCAN_NB) ? bsum[r * 128 + i] : 0;
    sm[t] = v;
    __syncthreads();
    for (int d = 1; d < 128; d <<= 1) {
        int add = (i >= d) ? sm[t - d] : 0;
        __syncthreads();
        sm[t] += add;
        __syncthreads();
    }
    int excl = (i == 0) ? 0 : sm[t - 1];
    if (i < SCAN_NB) bsum[r * 128 + i] = excl;
}
__global__ void scan_p3(const int* __restrict__ deg, const int* __restrict__ bsum,
                        int* __restrict__ off, int* __restrict__ cur) {
    int r = blockIdx.y, b = blockIdx.x, t = threadIdx.x;
    const int* d = deg + (size_t)r * N_NODES;
    int* o = off + (size_t)r * (N_NODES + 1);
    int* c = cur + (size_t)r * N_NODES;
    int base = b * 1024 + t * 4;
    int v[4], pre[4];
    int s = 0;
#pragma unroll
    for (int j = 0; j < 4; j++) {
        int idx = base + j;
        v[j] = (idx < N_NODES) ? d[idx] : 0;
        pre[j] = s;
        s += v[j];
    }
    __shared__ int sm[256];
    sm[t] = s;
    __syncthreads();
    for (int dd = 1; dd < 256; dd <<= 1) {
        int add = (t >= dd) ? sm[t - dd] : 0;
        __syncthreads();
        sm[t] += add;
        __syncthreads();
    }
    int texcl = (t == 0) ? 0 : sm[t - 1];
    int boff = bsum[r * 128 + b];
#pragma unroll
    for (int j = 0; j < 4; j++) {
        int idx = base + j;
        if (idx < N_NODES) {
            int val = boff + texcl + pre[j];
            o[idx] = val;
            c[idx] = val;
        }
    }
    if (b == SCAN_NB - 1 && t == 255) o[N_NODES] = boff + sm[255];
}

__global__ void fill_all_kernel(const int* __restrict__ e0, const int* __restrict__ e1,
                                const int* __restrict__ e2, const int* __restrict__ e3,
                                int* __restrict__ cur, int* __restrict__ csr) {
    int r = blockIdx.y;
    const int* eptr = (r == 0) ? e0 : (r == 1) ? e1 : (r == 2) ? e2 : e3;
    int i = blockIdx.x * 256 + threadIdx.x;
    if (i < N_EDGES) {
        int dnode = eptr[N_EDGES + i];
        int pos = atomicAdd(&cur[(size_t)r * N_NODES + dnode], 1);
        csr[(size_t)r * N_EDGES + pos] = eptr[i];
    }
}

// ---------------- conversion kernels ----------------
__global__ void conv_x_kernel(const float* __restrict__ x, __half* __restrict__ x16, int n) {
    int i = blockIdx.x * blockDim.x + threadIdx.x;
    if (i < n) x16[i] = __float2half(x[i]);
}
__global__ void split_w_kernel(const float* __restrict__ emb_w,
                               const float* __restrict__ root_w,
                               const float* __restrict__ conv_w,
                               __half* __restrict__ whi,
                               __half* __restrict__ wlo) {
    int idx = blockIdx.x * blockDim.x + threadIdx.x;
    if (idx >= 21 * 128 * 128) return;
    int s = idx >> 14;
    int rem = idx & 16383;
    int n = rem >> 7;
    int k = rem & 127;
    float v;
    if (s == 0)      v = (k < IN_FEAT) ? emb_w[(size_t)k * EMB + n] : 0.0f;
    else if (s <= 4) v = root_w[((size_t)(s - 1) * EMB + k) * EMB + n];
    else             v = conv_w[((size_t)(s - 5) * EMB + k) * EMB + n];
    __half h = __float2half(v);
    whi[idx] = h;
    wlo[idx] = __float2half(v - __half2float(h));
}

// ---------------- fp16x2 mma.sync GEMM: C[M,128] = A[M,K] @ W^T + bias ----------------
// A fp16 single; W = W_hi + W_lo (fp16 residual). Two passes: A*W_hi + A*W_lo.
// B (both tiles, full K) preloaded to smem once; k-loop streams A via cp.async.
// blockIdx.y selects slot/output. mode: 0 = y0 conv->Ch0, 1 = y0 root->Cf(+bias),
// 2 = y0 embed->Oh fp16 (+bias).
#define BK 32
#define SSTR 40
#define BSTR 136
#define A_TILE_E (128 * SSTR)
#define A_TILE_B (A_TILE_E * 2)
#define B_TILE_E (128 * BSTR)
#define B_TILE_B (B_TILE_E * 2)
#define GEMM_SMEM (2 * B_TILE_B + 2 * A_TILE_B)   // 69632 + 20480 = 90112

__global__ __launch_bounds__(256, 2) void gemm_mma(
    const __half* __restrict__ A, int M, int K,
    const __half* __restrict__ whi_base, const __half* __restrict__ wlo_base,
    int slotA, int slotB, int slotC, int mode,
    const float* __restrict__ bias0,
    float* __restrict__ Cf,
    __half* __restrict__ Ch0, __half* __restrict__ Ch1, __half* __restrict__ Ch2,
    __half* __restrict__ Oh)
{
    extern __shared__ __half sm_dyn[];
    uint32_t bs_u = smem_u32(sm_dyn);                     // B hi, then B lo
    uint32_t as_u = bs_u + 2 * B_TILE_B;                  // A stages

    int y = blockIdx.y;
    int slot = (y == 0) ? slotA : (y == 1) ? slotB : slotC;
    const __half* Whi = whi_base + (size_t)slot * 16384;
    const __half* Wlo = wlo_base + (size_t)slot * 16384;

    int tid = threadIdx.x;
    int wid = tid >> 5;
    int lane = tid & 31;
    int wm = wid & 1;
    int wn = wid >> 1;
    int r0 = blockIdx.x * 128;

    // ---- preload B hi+lo (full 128x128) into smem ----
    for (int idx = tid; idx < 2048; idx += 256) {
        int row = idx >> 4;
        int ch = idx & 15;
        uint32_t soff = (uint32_t)(row * BSTR + ch * 8) * 2u;
        CP_ASYNC16(bs_u + soff,
                   (uint64_t)__cvta_generic_to_global(Whi + (size_t)row * 128 + ch * 8), 16);
        CP_ASYNC16(bs_u + B_TILE_B + soff,
                   (uint64_t)__cvta_generic_to_global(Wlo + (size_t)row * 128 + ch * 8), 16);
    }
    asm volatile("cp.async.commit_group;");

    float acc[4][4][4];
#pragma unroll
    for (int i = 0; i < 4; i++)
#pragma unroll
        for (int j = 0; j < 4; j++)
#pragma unroll
            for (int q = 0; q < 4; q++) acc[i][j][q] = 0.0f;

    int l_within = lane & 7;
    int l_sel = lane >> 3;
    int nch = K >> 5;

    int li0 = tid * 2, li1 = tid * 2 + 1;
    int lr0 = li0 >> 2, lc0 = li0 & 3;
    int lr1 = li1 >> 2, lc1 = li1 & 3;

    auto load_stage = [&](int kc, int st) {
        int k0 = kc * BK;
#pragma unroll
        for (int i = 0; i < 2; i++) {
            int row = i ? lr1 : lr0;
            int ch  = i ? lc1 : lc0;
            int gr = r0 + row;
            int ok = (gr < M) ? 16 : 0;
            int grc = (gr < M) ? gr : 0;
            uint32_t soff = (uint32_t)(row * SSTR + ch * 8) * 2u;
            CP_ASYNC16(as_u + (uint32_t)st * A_TILE_B + soff,
                       (uint64_t)__cvta_generic_to_global(A + (size_t)grc * K + k0 + ch * 8), ok);
        }
        asm volatile("cp.async.commit_group;");
    };

    load_stage(0, 0);
    for (int kc = 0; kc < nch; kc++) {
        int st = kc & 1;
        if (kc + 1 < nch) {
            load_stage(kc + 1, st ^ 1);
            asm volatile("cp.async.wait_group 1;");
        } else {
            asm volatile("cp.async.wait_group 0;");
        }
        __syncthreads();

        uint32_t a_stage = as_u + (uint32_t)st * A_TILE_B;
#pragma unroll
        for (int pass = 0; pass < 2; pass++) {
            uint32_t b_base = bs_u + (uint32_t)pass * B_TILE_B;
#pragma unroll
            for (int ks = 0; ks < 2; ks++) {
                uint32_t af[4][4];
                uint32_t bf[4][2];
#pragma unroll
                for (int fm = 0; fm < 4; fm++) {
                    int arow = wm * 64 + fm * 16 + (l_sel & 1) * 8 + l_within;
                    int acol = ks * 16 + (l_sel >> 1) * 8;
                    ldsm4(af[fm][0], af[fm][1], af[fm][2], af[fm][3],
                          a_stage + (uint32_t)(arow * SSTR + acol) * 2u);
                }
#pragma unroll
                for (int g = 0; g < 2; g++) {
                    int brow = wn * 32 + g * 16 + (l_sel >> 1) * 8 + l_within;
                    int bcol = kc * 32 + ks * 16 + (l_sel & 1) * 8;
                    uint32_t r0v, r1v, r2v, r3v;
                    ldsm4(r0v, r1v, r2v, r3v,
                          b_base + (uint32_t)(brow * BSTR + bcol) * 2u);
                    bf[2 * g + 0][0] = r0v; bf[2 * g + 0][1] = r1v;
                    bf[2 * g + 1][0] = r2v; bf[2 * g + 1][1] = r3v;
                }
#pragma unroll
                for (int fm = 0; fm < 4; fm++)
#pragma unroll
                    for (int fn = 0; fn < 4; fn++)
                        mma16816(acc[fm][fn], af[fm], bf[fn]);
            }
        }
        __syncthreads();
    }

    // ---- epilogue ----
    int qrow = lane >> 2;
    int qcol = (lane & 3) * 2;
    bool is_root  = (y == 0) && (mode == 1);
    bool is_embed = (y == 0) && (mode == 2);
    __half* Ch = (y == 0) ? Ch0 : (y == 1) ? Ch1 : Ch2;
#pragma unroll
    for (int fm = 0; fm < 4; fm++) {
#pragma unroll
        for (int half_i = 0; half_i < 2; half_i++) {
            int grow = r0 + wm * 64 + fm * 16 + qrow + half_i * 8;
            if (grow >= M) continue;
#pragma unroll
            for (int fn = 0; fn < 4; fn++) {
                int col = wn * 32 + fn * 8 + qcol;
                float v0 = acc[fm][fn][half_i * 2 + 0];
                float v1 = acc[fm][fn][half_i * 2 + 1];
                if (is_root || is_embed) {
                    v0 += __ldg(&bias0[col]);
                    v1 += __ldg(&bias0[col + 1]);
                }
                if (is_root) {
                    float2 fv; fv.x = v0; fv.y = v1;
                    *(float2*)(Cf + (size_t)grow * EMB + col) = fv;
                } else if (is_embed) {
                    *(__half2*)(Oh + (size_t)grow * EMB + col) = __floats2half2_rn(v0, v1);
                } else {
                    *(__half2*)(Ch + (size_t)grow * EMB + col) = __floats2half2_rn(v0, v1);
                }
            }
        }
    }
}

// ---------------- pair-fused aggregation (warp per node, fp16 messages) ----------------
__device__ __forceinline__ void agg_one_rel(
    const __half* __restrict__ msg, const int* __restrict__ off,
    const int* __restrict__ csr, int node, int lane, float4& acc)
{
    int s = __ldg(&off[node]);
    int e = __ldg(&off[node + 1]);
    if (s >= e) return;
    float4 m = make_float4(-FLT_MAX, -FLT_MAX, -FLT_MAX, -FLT_MAX);
    int i = s;
    for (; i + 1 < e; i += 2) {
        int s0 = __ldg(&csr[i]);
        int s1 = __ldg(&csr[i + 1]);
        uint2 u0 = *(const uint2*)(msg + (size_t)s0 * EMB + lane * 4);
        uint2 u1 = *(const uint2*)(msg + (size_t)s1 * EMB + lane * 4);
        float2 a0 = __half22float2(*(__half2*)&u0.x);
        float2 b0 = __half22float2(*(__half2*)&u0.y);
        float2 a1 = __half22float2(*(__half2*)&u1.x);
        float2 b1 = __half22float2(*(__half2*)&u1.y);
        m.x = fmaxf(m.x, fmaxf(a0.x, a1.x));
        m.y = fmaxf(m.y, fmaxf(a0.y, a1.y));
        m.z = fmaxf(m.z, fmaxf(b0.x, b1.x));
        m.w = fmaxf(m.w, fmaxf(b0.y, b1.y));
    }
    if (i < e) {
        int s0 = __ldg(&csr[i]);
        uint2 u0 = *(const uint2*)(msg + (size_t)s0 * EMB + lane * 4);
        float2 a0 = __half22float2(*(__half2*)&u0.x);
        float2 b0 = __half22float2(*(__half2*)&u0.y);
        m.x = fmaxf(m.x, a0.x);
        m.y = fmaxf(m.y, a0.y);
        m.z = fmaxf(m.z, b0.x);
        m.w = fmaxf(m.w, b0.y);
    }
    acc.x += m.x; acc.y += m.y; acc.z += m.z; acc.w += m.w;
}

__global__ __launch_bounds__(256) void agg_pair_kernel(
    const __half* __restrict__ msg0, const __half* __restrict__ msg1,
    const int* __restrict__ off0, const int* __restrict__ csr0,
    const int* __restrict__ off1, const int* __restrict__ csr1,
    float* __restrict__ outbuf, float* __restrict__ hOut,
    __half* __restrict__ h16,
    int last, int write_f32)
{
    int node = blockIdx.x * 8 + (threadIdx.x >> 5);
    if (node >= N_NODES) return;
    int lane = threadIdx.x & 31;
    size_t base = (size_t)node * EMB + lane * 4;

    float4 acc = __ldcs((const float4*)(outbuf + base));

    agg_one_rel(msg0, off0, csr0, node, lane, acc);
    agg_one_rel(msg1, off1, csr1, node, lane, acc);

    if (!last) {
        __stcs((float4*)(outbuf + base), acc);
        return;
    }

    acc.x = fmaxf(acc.x, 0.0f);
    acc.y = fmaxf(acc.y, 0.0f);
    acc.z = fmaxf(acc.z, 0.0f);
    acc.w = fmaxf(acc.w, 0.0f);

    if (write_f32) *(float4*)(hOut + base) = acc;

    *(__half2*)(h16 + base) = __floats2half2_rn(acc.x, acc.y);
    *(__half2*)(h16 + base + 2) = __floats2half2_rn(acc.z, acc.w);
}

// ---------------- global add pool ----------------
__global__ __launch_bounds__(128) void pool_kernel(
    const float* __restrict__ h, const int* __restrict__ batch,
    float* __restrict__ out, int n)
{
    const int NPB = 256;
    int f = threadIdx.x;
    int n0 = blockIdx.x * NPB;
    if (n0 >= n) return;
    int nend = min(n0 + NPB, n);
    float acc = 0.0f;
    int cur = batch[n0];
    for (int i = n0; i < nend; i++) {
        int b = batch[i];
        if (b != cur) {
            atomicAdd(&out[(size_t)cur * EMB + f], acc);
            acc = 0.0f;
            cur = b;
        }
        acc += h[(size_t)i * EMB + f];
    }
    atomicAdd(&out[(size_t)cur * EMB + f], acc);
}

// ---------------- host launch ----------------
extern "C" void kernel_launch(void* const* d_in, const int* in_sizes, int n_in,
                              void* d_out, int out_size)
{
    const float* x      = (const float*)d_in[0];
    const int*   e0     = (const int*)d_in[1];
    const int*   e1     = (const int*)d_in[2];
    const int*   e2     = (const int*)d_in[3];
    const int*   e3     = (const int*)d_in[4];
    const int*   batch  = (const int*)d_in[5];
    const float* emb_w  = (const float*)d_in[6];
    const float* emb_b  = (const float*)d_in[7];
    const float* root_w = (const float*)d_in[8];
    const float* root_b = (const float*)d_in[9];
    const float* conv_w = (const float*)d_in[10];
    float* out = (float*)d_out;

    void *p_h, *p_out, *p_t0, *p_t1, *p_h16, *p_x16, *p_whi, *p_wlo;
    void *p_csr, *p_deg, *p_off, *p_cur, *p_bsum;
    cudaGetSymbolAddress(&p_h, g_h);
    cudaGetSymbolAddress(&p_out, g_out);
    cudaGetSymbolAddress(&p_t0, g_tmp0);
    cudaGetSymbolAddress(&p_t1, g_tmp1);
    cudaGetSymbolAddress(&p_h16, g_h16);
    cudaGetSymbolAddress(&p_x16, g_x16);
    cudaGetSymbolAddress(&p_whi, g_w_hi);
    cudaGetSymbolAddress(&p_wlo, g_w_lo);
    cudaGetSymbolAddress(&p_csr, g_csr_src);
    cudaGetSymbolAddress(&p_deg, g_deg);
    cudaGetSymbolAddress(&p_off, g_off);
    cudaGetSymbolAddress(&p_cur, g_cur);
    cudaGetSymbolAddress(&p_bsum, g_bsum);
    float* h_buf  = (float*)p_h;
    float* out_buf = (float*)p_out;
    __half* tmp0 = (__half*)p_t0;
    __half* tmp1 = (__half*)p_t1;
    __half* h16  = (__half*)p_h16;
    __half* x16  = (__half*)p_x16;
    __half* w_hi = (__half*)p_whi;
    __half* w_lo = (__half*)p_wlo;
    int* csr = (int*)p_csr;
    int* deg = (int*)p_deg;
    int* off = (int*)p_off;
    int* cur = (int*)p_cur;
    int* bsum = (int*)p_bsum;

    static bool attr_set = []() {
        cudaFuncSetAttribute(gemm_mma, cudaFuncAttributeMaxDynamicSharedMemorySize, GEMM_SMEM);
        return true;
    }();
    (void)attr_set;

    static cudaStream_t s2 = []() {
        cudaStream_t s;
        cudaStreamCreateWithFlags(&s, cudaStreamNonBlocking);
        return s;
    }();
    static cudaEvent_t evFork = []() {
        cudaEvent_t e; cudaEventCreateWithFlags(&e, cudaEventDisableTiming); return e;
    }();
    static cudaEvent_t evCsr = []() {
        cudaEvent_t e; cudaEventCreateWithFlags(&e, cudaEventDisableTiming); return e;
    }();

    const int EB = (N_EDGES + 255) / 256;
    const int GB = (N_NODES + 127) / 128;
    const int AB = (N_NODES + 7) / 8;

    // ---- fork CSR build to s2 (overlaps with conversions + embed GEMM) ----
    cudaEventRecord(evFork, 0);
    cudaStreamWaitEvent(s2, evFork, 0);
    zero_int_kernel<<<(N_REL * N_NODES + 255) / 256, 256, 0, s2>>>(deg, N_REL * N_NODES);
    hist_all_kernel<<<dim3(EB, N_REL), 256, 0, s2>>>(e0, e1, e2, e3, deg);
    scan_p1<<<dim3(SCAN_NB, N_REL), 256, 0, s2>>>(deg, bsum);
    scan_p2<<<1, 512, 0, s2>>>(bsum);
    scan_p3<<<dim3(SCAN_NB, N_REL), 256, 0, s2>>>(deg, bsum, off, cur);
    fill_all_kernel<<<dim3(EB, N_REL), 256, 0, s2>>>(e0, e1, e2, e3, cur, csr);
    cudaEventRecord(evCsr, s2);

    // ---- main stream: conversions + embed ----
    split_w_kernel<<<(21 * 128 * 128 + 255) / 256, 256>>>(emb_w, root_w, conv_w, w_hi, w_lo);
    conv_x_kernel<<<(N_NODES * IN_FEAT + 255) / 256, 256>>>(x, x16, N_NODES * IN_FEAT);
    // embed: h16 = fp16(x @ emb_w + emb_b)
    gemm_mma<<<dim3(GB, 1), 256, GEMM_SMEM>>>(x16, N_NODES, IN_FEAT, w_hi, w_lo,
                                              0, 0, 0, /*mode=*/2, emb_b,
                                              (float*)0, (__half*)0, (__half*)0, (__half*)0,
                                              h16);

    bool joined = false;
    for (int l = 0; l < N_LAYERS; l++) {
        int cb = 5 + l * N_REL;
        // root + conv0 + conv1 (batched)
        gemm_mma<<<dim3(GB, 3), 256, GEMM_SMEM>>>(h16, N_NODES, EMB, w_hi, w_lo,
                                                  1 + l, cb, cb + 1, /*mode=*/1,
                                                  root_b + (size_t)l * EMB,
                                                  out_buf, (__half*)0, tmp0, tmp1,
                                                  (__half*)0);
        if (!joined) {
            cudaStreamWaitEvent(0, evCsr, 0);
            joined = true;
        }
        agg_pair_kernel<<<AB, 256>>>(tmp0, tmp1,
                                     off, csr,
                                     off + (size_t)(N_NODES + 1), csr + (size_t)N_EDGES,
                                     out_buf, h_buf, h16, 0, 0);
        // conv2 + conv3 (batched, reuse tmp buffers)
        gemm_mma<<<dim3(GB, 2), 256, GEMM_SMEM>>>(h16, N_NODES, EMB, w_hi, w_lo,
                                                  cb + 2, cb + 3, 0, /*mode=*/0,
                                                  (const float*)0,
                                                  (float*)0, tmp0, tmp1, (__half*)0,
                                                  (__half*)0);
        agg_pair_kernel<<<AB, 256>>>(tmp0, tmp1,
                                     off + (size_t)2 * (N_NODES + 1), csr + (size_t)2 * N_EDGES,
                                     off + (size_t)3 * (N_NODES + 1), csr + (size_t)3 * N_EDGES,
                                     out_buf, h_buf, h16, 1,
                                     (l == N_LAYERS - 1) ? 1 : 0);
    }

    // ---- global add pool ----
    zero_float_kernel<<<(N_GRAPHS * EMB + 255) / 256, 256>>>(out, N_GRAPHS * EMB);
    pool_kernel<<<(N_NODES + 255) / 256, 128>>>(h_buf, batch, out, N_NODES);
}

// round 11
// speedup vs baseline: 2.4012x; 1.1616x over previous
#include <cuda_runtime.h>
#include <cuda_fp16.h>
#include <cstdint>
#include <cfloat>

#define N_NODES 100000
#define N_EDGES 500000
#define N_REL 4
#define N_LAYERS 4
#define IN_FEAT 64
#define EMB 128
#define N_GRAPHS 64
#define SCAN_NB 98   // ceil(100000/1024)

// ---------------- scratch (device globals; no allocation allowed) ----------------
__device__ float  g_h[(size_t)N_NODES * EMB];     // final-layer h fp32 (for pool)
__device__ float  g_out[(size_t)N_NODES * EMB];   // layer accumulator fp32
__device__ __half g_tmp[(size_t)N_REL * N_NODES * EMB];  // 4 conv outputs fp16 (102MB, L2-resident)
__device__ __half g_h16[(size_t)N_NODES * EMB];   // h fp16 (GEMM A operand)
__device__ __half g_x16[(size_t)N_NODES * IN_FEAT];
// 21 weight matrices, transposed [N=128][K=128] fp16:
// slot 0 = emb (K rows 64..127 zero), 1..4 = root, 5..20 = conv (l*4+r)
__device__ __half g_w16[(size_t)21 * 128 * 128];
__device__ int   g_csr_src[(size_t)N_REL * N_EDGES];
__device__ int   g_deg[(size_t)N_REL * N_NODES];
__device__ int   g_off[(size_t)N_REL * (N_NODES + 1)];
__device__ int   g_cur[(size_t)N_REL * N_NODES];
__device__ int   g_bsum[(size_t)N_REL * 128];

// ---------------- helpers ----------------
__device__ __forceinline__ uint32_t smem_u32(const void* p) {
    uint32_t a;
    asm("{ .reg .u64 t; cvta.to.shared.u64 t, %1; cvt.u32.u64 %0, t; }" : "=r"(a) : "l"(p));
    return a;
}
__device__ __forceinline__ void ldsm4(uint32_t& r0, uint32_t& r1, uint32_t& r2, uint32_t& r3,
                                      uint32_t addr) {
    asm volatile("ldmatrix.sync.aligned.m8n8.x4.shared.b16 {%0,%1,%2,%3}, [%4];"
                 : "=r"(r0), "=r"(r1), "=r"(r2), "=r"(r3) : "r"(addr));
}
__device__ __forceinline__ void mma16816(float* d, const uint32_t* a, const uint32_t* b) {
    asm volatile(
        "mma.sync.aligned.m16n8k16.row.col.f32.f16.f16.f32 "
        "{%0,%1,%2,%3}, {%4,%5,%6,%7}, {%8,%9}, {%0,%1,%2,%3};"
        : "+f"(d[0]), "+f"(d[1]), "+f"(d[2]), "+f"(d[3])
        : "r"(a[0]), "r"(a[1]), "r"(a[2]), "r"(a[3]), "r"(b[0]), "r"(b[1]));
}
#define CP_ASYNC16(dst, src, n) \
    asm volatile("cp.async.ca.shared.global [%0], [%1], 16, %2;" \
                 :: "r"(dst), "l"(src), "r"(n))

// ---------------- utility kernels ----------------
__global__ void zero_int_kernel(int* p, int n) {
    int i = blockIdx.x * blockDim.x + threadIdx.x;
    if (i < n) p[i] = 0;
}
__global__ void zero_float_kernel(float* p, int n) {
    int i = blockIdx.x * blockDim.x + threadIdx.x;
    if (i < n) p[i] = 0.0f;
}

__global__ void hist_all_kernel(const int* __restrict__ e0, const int* __restrict__ e1,
                                const int* __restrict__ e2, const int* __restrict__ e3,
                                int* __restrict__ deg) {
    int r = blockIdx.y;
    const int* dst = ((r == 0) ? e0 : (r == 1) ? e1 : (r == 2) ? e2 : e3) + N_EDGES;
    int i = blockIdx.x * 256 + threadIdx.x;
    if (i < N_EDGES) atomicAdd(&deg[(size_t)r * N_NODES + dst[i]], 1);
}

// -------- 3-phase parallel exclusive scan of deg -> off (all relations) --------
__global__ void scan_p1(const int* __restrict__ deg, int* __restrict__ bsum) {
    int r = blockIdx.y, b = blockIdx.x, t = threadIdx.x;
    const int* d = deg + (size_t)r * N_NODES;
    int base = b * 1024 + t * 4;
    int s = 0;
#pragma unroll
    for (int j = 0; j < 4; j++) {
        int idx = base + j;
        if (idx < N_NODES) s += d[idx];
    }
    __shared__ int sm[256];
    sm[t] = s;
    __syncthreads();
    for (int o = 128; o > 0; o >>= 1) {
        if (t < o) sm[t] += sm[t + o];
        __syncthreads();
    }
    if (t == 0) bsum[r * 128 + b] = sm[0];
}
__global__ void scan_p2(int* __restrict__ bsum) {
    __shared__ int sm[512];
    int t = threadIdx.x;
    int r = t >> 7;
    int i = t & 127;
    int v = (i < SCAN_NB) ? bsum[r * 128 + i] : 0;
    sm[t] = v;
    __syncthreads();
    for (int d = 1; d < 128; d <<= 1) {
        int add = (i >= d) ? sm[t - d] : 0;
        __syncthreads();
        sm[t] += add;
        __syncthreads();
    }
    int excl = (i == 0) ? 0 : sm[t - 1];
    if (i < SCAN_NB) bsum[r * 128 + i] = excl;
}
__global__ void scan_p3(const int* __restrict__ deg, const int* __restrict__ bsum,
                        int* __restrict__ off, int* __restrict__ cur) {
    int r = blockIdx.y, b = blockIdx.x, t = threadIdx.x;
    const int* d = deg + (size_t)r * N_NODES;
    int* o = off + (size_t)r * (N_NODES + 1);
    int* c = cur + (size_t)r * N_NODES;
    int base = b * 1024 + t * 4;
    int v[4], pre[4];
    int s = 0;
#pragma unroll
    for (int j = 0; j < 4; j++) {
        int idx = base + j;
        v[j] = (idx < N_NODES) ? d[idx] : 0;
        pre[j] = s;
        s += v[j];
    }
    __shared__ int sm[256];
    sm[t] = s;
    __syncthreads();
    for (int dd = 1; dd < 256; dd <<= 1) {
        int add = (t >= dd) ? sm[t - dd] : 0;
        __syncthreads();
        sm[t] += add;
        __syncthreads();
    }
    int texcl = (t == 0) ? 0 : sm[t - 1];
    int boff = bsum[r * 128 + b];
#pragma unroll
    for (int j = 0; j < 4; j++) {
        int idx = base + j;
        if (idx < N_NODES) {
            int val = boff + texcl + pre[j];
            o[idx] = val;
            c[idx] = val;
        }
    }
    if (b == SCAN_NB - 1 && t == 255) o[N_NODES] = boff + sm[255];
}

__global__ void fill_all_kernel(const int* __restrict__ e0, const int* __restrict__ e1,
                                const int* __restrict__ e2, const int* __restrict__ e3,
                                int* __restrict__ cur, int* __restrict__ csr) {
    int r = blockIdx.y;
    const int* eptr = (r == 0) ? e0 : (r == 1) ? e1 : (r == 2) ? e2 : e3;
    int i = blockIdx.x * 256 + threadIdx.x;
    if (i < N_EDGES) {
        int dnode = eptr[N_EDGES + i];
        int pos = atomicAdd(&cur[(size_t)r * N_NODES + dnode], 1);
        csr[(size_t)r * N_EDGES + pos] = eptr[i];
    }
}

// ---------------- conversion kernels ----------------
__global__ void conv_x_kernel(const float* __restrict__ x, __half* __restrict__ x16, int n) {
    int i = blockIdx.x * blockDim.x + threadIdx.x;
    if (i < n) x16[i] = __float2half(x[i]);
}
__global__ void conv_w_kernel(const float* __restrict__ emb_w,
                              const float* __restrict__ root_w,
                              const float* __restrict__ conv_w,
                              __half* __restrict__ w16) {
    int idx = blockIdx.x * blockDim.x + threadIdx.x;
    if (idx >= 21 * 128 * 128) return;
    int s = idx >> 14;
    int rem = idx & 16383;
    int n = rem >> 7;
    int k = rem & 127;
    float v;
    if (s == 0)      v = (k < IN_FEAT) ? emb_w[(size_t)k * EMB + n] : 0.0f;
    else if (s <= 4) v = root_w[((size_t)(s - 1) * EMB + k) * EMB + n];
    else             v = conv_w[((size_t)(s - 5) * EMB + k) * EMB + n];
    w16[idx] = __float2half(v);
}

// ---------------- fp16 mma.sync GEMM: C[M,128] = A[M,K] @ W^T + bias ----------------
// Single fp16 pass. B preloaded to smem once (full K); k-loop streams A via cp.async.
// slot selection: mode==1 (layer batch): y==0 -> root slot (slotArg>>16), writes Cf+bias;
//   y==1..4 -> conv slot (slotArg&0xFFFF)+y, writes Ch + (y-1)*MN as fp16.
// mode==2 (embed): slot = slotArg, writes Oh fp16 (+bias).
#define BK 32
#define SSTR 40
#define BSTR 136
#define A_TILE_E (128 * SSTR)
#define A_TILE_B (A_TILE_E * 2)
#define B_TILE_B (128 * BSTR * 2)
#define GEMM_SMEM (B_TILE_B + 2 * A_TILE_B)   // 34816 + 20480 = 55296

__global__ __launch_bounds__(256, 2) void gemm_mma(
    const __half* __restrict__ A, int M, int K,
    const __half* __restrict__ w_base, int slotArg, int mode,
    const float* __restrict__ bias0,
    float* __restrict__ Cf,
    __half* __restrict__ Ch,
    __half* __restrict__ Oh)
{
    extern __shared__ __half sm_dyn[];
    uint32_t bs_u = smem_u32(sm_dyn);
    uint32_t as_u = bs_u + B_TILE_B;

    int y = blockIdx.y;
    int slot = (mode == 1) ? ((y == 0) ? (slotArg >> 16) : ((slotArg & 0xFFFF) + y))
                           : slotArg;
    const __half* W = w_base + (size_t)slot * 16384;

    int tid = threadIdx.x;
    int wid = tid >> 5;
    int lane = tid & 31;
    int wm = wid & 1;
    int wn = wid >> 1;
    int r0 = blockIdx.x * 128;

    // ---- preload B (full 128x128) into smem ----
    for (int idx = tid; idx < 2048; idx += 256) {
        int row = idx >> 4;
        int ch = idx & 15;
        uint32_t soff = (uint32_t)(row * BSTR + ch * 8) * 2u;
        CP_ASYNC16(bs_u + soff,
                   (uint64_t)__cvta_generic_to_global(W + (size_t)row * 128 + ch * 8), 16);
    }
    asm volatile("cp.async.commit_group;");

    float acc[4][4][4];
#pragma unroll
    for (int i = 0; i < 4; i++)
#pragma unroll
        for (int j = 0; j < 4; j++)
#pragma unroll
            for (int q = 0; q < 4; q++) acc[i][j][q] = 0.0f;

    int l_within = lane & 7;
    int l_sel = lane >> 3;
    int nch = K >> 5;

    int li0 = tid * 2, li1 = tid * 2 + 1;
    int lr0 = li0 >> 2, lc0 = li0 & 3;
    int lr1 = li1 >> 2, lc1 = li1 & 3;

    auto load_stage = [&](int kc, int st) {
        int k0 = kc * BK;
#pragma unroll
        for (int i = 0; i < 2; i++) {
            int row = i ? lr1 : lr0;
            int ch  = i ? lc1 : lc0;
            int gr = r0 + row;
            int ok = (gr < M) ? 16 : 0;
            int grc = (gr < M) ? gr : 0;
            uint32_t soff = (uint32_t)(row * SSTR + ch * 8) * 2u;
            CP_ASYNC16(as_u + (uint32_t)st * A_TILE_B + soff,
                       (uint64_t)__cvta_generic_to_global(A + (size_t)grc * K + k0 + ch * 8), ok);
        }
        asm volatile("cp.async.commit_group;");
    };

    load_stage(0, 0);
    for (int kc = 0; kc < nch; kc++) {
        int st = kc & 1;
        if (kc + 1 < nch) {
            load_stage(kc + 1, st ^ 1);
            asm volatile("cp.async.wait_group 1;");
        } else {
            asm volatile("cp.async.wait_group 0;");
        }
        __syncthreads();

        uint32_t a_stage = as_u + (uint32_t)st * A_TILE_B;
#pragma unroll
        for (int ks = 0; ks < 2; ks++) {
            uint32_t af[4][4];
            uint32_t bf[4][2];
#pragma unroll
            for (int fm = 0; fm < 4; fm++) {
                int arow = wm * 64 + fm * 16 + (l_sel & 1) * 8 + l_within;
                int acol = ks * 16 + (l_sel >> 1) * 8;
                ldsm4(af[fm][0], af[fm][1], af[fm][2], af[fm][3],
                      a_stage + (uint32_t)(arow * SSTR + acol) * 2u);
            }
#pragma unroll
            for (int g = 0; g < 2; g++) {
                int brow = wn * 32 + g * 16 + (l_sel >> 1) * 8 + l_within;
                int bcol = kc * 32 + ks * 16 + (l_sel & 1) * 8;
                uint32_t r0v, r1v, r2v, r3v;
                ldsm4(r0v, r1v, r2v, r3v,
                      bs_u + (uint32_t)(brow * BSTR + bcol) * 2u);
                bf[2 * g + 0][0] = r0v; bf[2 * g + 0][1] = r1v;
                bf[2 * g + 1][0] = r2v; bf[2 * g + 1][1] = r3v;
            }
#pragma unroll
            for (int fm = 0; fm < 4; fm++)
#pragma unroll
                for (int fn = 0; fn < 4; fn++)
                    mma16816(acc[fm][fn], af[fm], bf[fn]);
        }
        __syncthreads();
    }

    // ---- epilogue ----
    int qrow = lane >> 2;
    int qcol = (lane & 3) * 2;
    bool is_root  = (mode == 1) && (y == 0);
    bool is_embed = (mode == 2);
    __half* ChL = Ch + ((mode == 1 && y > 0) ? ((size_t)(y - 1) * (size_t)N_NODES * EMB)
                                             : (size_t)0);
#pragma unroll
    for (int fm = 0; fm < 4; fm++) {
#pragma unroll
        for (int half_i = 0; half_i < 2; half_i++) {
            int grow = r0 + wm * 64 + fm * 16 + qrow + half_i * 8;
            if (grow >= M) continue;
#pragma unroll
            for (int fn = 0; fn < 4; fn++) {
                int col = wn * 32 + fn * 8 + qcol;
                float v0 = acc[fm][fn][half_i * 2 + 0];
                float v1 = acc[fm][fn][half_i * 2 + 1];
                if (is_root || is_embed) {
                    v0 += __ldg(&bias0[col]);
                    v1 += __ldg(&bias0[col + 1]);
                }
                if (is_root) {
                    float2 fv; fv.x = v0; fv.y = v1;
                    *(float2*)(Cf + (size_t)grow * EMB + col) = fv;
                } else if (is_embed) {
                    *(__half2*)(Oh + (size_t)grow * EMB + col) = __floats2half2_rn(v0, v1);
                } else {
                    *(__half2*)(ChL + (size_t)grow * EMB + col) = __floats2half2_rn(v0, v1);
                }
            }
        }
    }
}

// ---------------- fully-fused per-layer aggregation (warp per node) ----------------
__global__ __launch_bounds__(256) void agg_fused_kernel(
    const __half* __restrict__ tmp, const int* __restrict__ off,
    const int* __restrict__ csr, float* __restrict__ outbuf,
    float* __restrict__ hOut, __half* __restrict__ h16,
    int write_f32)
{
    int node = blockIdx.x * 8 + (threadIdx.x >> 5);
    if (node >= N_NODES) return;
    int lane = threadIdx.x & 31;
    size_t base = (size_t)node * EMB + lane * 4;

    int s[N_REL], e[N_REL];
#pragma unroll
    for (int r = 0; r < N_REL; r++) {
        const int* offr = off + (size_t)r * (N_NODES + 1);
        s[r] = __ldg(&offr[node]);
        e[r] = __ldg(&offr[node + 1]);
    }

    float4 acc = __ldcs((const float4*)(outbuf + base));

#pragma unroll
    for (int r = 0; r < N_REL; r++) {
        int i = s[r], ecnt = e[r];
        if (i >= ecnt) continue;
        const int* csrr = csr + (size_t)r * N_EDGES;
        const __half* msg = tmp + (size_t)r * (size_t)N_NODES * EMB;
        float4 m = make_float4(-FLT_MAX, -FLT_MAX, -FLT_MAX, -FLT_MAX);
        for (; i + 1 < ecnt; i += 2) {
            int s0 = __ldg(&csrr[i]);
            int s1 = __ldg(&csrr[i + 1]);
            uint2 u0 = *(const uint2*)(msg + (size_t)s0 * EMB + lane * 4);
            uint2 u1 = *(const uint2*)(msg + (size_t)s1 * EMB + lane * 4);
            float2 a0 = __half22float2(*(__half2*)&u0.x);
            float2 b0 = __half22float2(*(__half2*)&u0.y);
            float2 a1 = __half22float2(*(__half2*)&u1.x);
            float2 b1 = __half22float2(*(__half2*)&u1.y);
            m.x = fmaxf(m.x, fmaxf(a0.x, a1.x));
            m.y = fmaxf(m.y, fmaxf(a0.y, a1.y));
            m.z = fmaxf(m.z, fmaxf(b0.x, b1.x));
            m.w = fmaxf(m.w, fmaxf(b0.y, b1.y));
        }
        if (i < ecnt) {
            int s0 = __ldg(&csrr[i]);
            uint2 u0 = *(const uint2*)(msg + (size_t)s0 * EMB + lane * 4);
            float2 a0 = __half22float2(*(__half2*)&u0.x);
            float2 b0 = __half22float2(*(__half2*)&u0.y);
            m.x = fmaxf(m.x, a0.x);
            m.y = fmaxf(m.y, a0.y);
            m.z = fmaxf(m.z, b0.x);
            m.w = fmaxf(m.w, b0.y);
        }
        acc.x += m.x; acc.y += m.y; acc.z += m.z; acc.w += m.w;
    }

    acc.x = fmaxf(acc.x, 0.0f);
    acc.y = fmaxf(acc.y, 0.0f);
    acc.z = fmaxf(acc.z, 0.0f);
    acc.w = fmaxf(acc.w, 0.0f);

    if (write_f32) __stcs((float4*)(hOut + base), acc);

    *(__half2*)(h16 + base) = __floats2half2_rn(acc.x, acc.y);
    *(__half2*)(h16 + base + 2) = __floats2half2_rn(acc.z, acc.w);
}

// ---------------- global add pool ----------------
__global__ __launch_bounds__(128) void pool_kernel(
    const float* __restrict__ h, const int* __restrict__ batch,
    float* __restrict__ out, int n)
{
    const int NPB = 256;
    int f = threadIdx.x;
    int n0 = blockIdx.x * NPB;
    if (n0 >= n) return;
    int nend = min(n0 + NPB, n);
    float acc = 0.0f;
    int cur = batch[n0];
    for (int i = n0; i < nend; i++) {
        int b = batch[i];
        if (b != cur) {
            atomicAdd(&out[(size_t)cur * EMB + f], acc);
            acc = 0.0f;
            cur = b;
        }
        acc += h[(size_t)i * EMB + f];
    }
    atomicAdd(&out[(size_t)cur * EMB + f], acc);
}

// ---------------- host launch ----------------
extern "C" void kernel_launch(void* const* d_in, const int* in_sizes, int n_in,
                              void* d_out, int out_size)
{
    const float* x      = (const float*)d_in[0];
    const int*   e0     = (const int*)d_in[1];
    const int*   e1     = (const int*)d_in[2];
    const int*   e2     = (const int*)d_in[3];
    const int*   e3     = (const int*)d_in[4];
    const int*   batch  = (const int*)d_in[5];
    const float* emb_w  = (const float*)d_in[6];
    const float* emb_b  = (const float*)d_in[7];
    const float* root_w = (const float*)d_in[8];
    const float* root_b = (const float*)d_in[9];
    const float* conv_w = (const float*)d_in[10];
    float* out = (float*)d_out;

    void *p_h, *p_out, *p_tmp, *p_h16, *p_x16, *p_w16;
    void *p_csr, *p_deg, *p_off, *p_cur, *p_bsum;
    cudaGetSymbolAddress(&p_h, g_h);
    cudaGetSymbolAddress(&p_out, g_out);
    cudaGetSymbolAddress(&p_tmp, g_tmp);
    cudaGetSymbolAddress(&p_h16, g_h16);
    cudaGetSymbolAddress(&p_x16, g_x16);
    cudaGetSymbolAddress(&p_w16, g_w16);
    cudaGetSymbolAddress(&p_csr, g_csr_src);
    cudaGetSymbolAddress(&p_deg, g_deg);
    cudaGetSymbolAddress(&p_off, g_off);
    cudaGetSymbolAddress(&p_cur, g_cur);
    cudaGetSymbolAddress(&p_bsum, g_bsum);
    float* h_buf  = (float*)p_h;
    float* out_buf = (float*)p_out;
    __half* tmp  = (__half*)p_tmp;
    __half* h16  = (__half*)p_h16;
    __half* x16  = (__half*)p_x16;
    __half* w16  = (__half*)p_w16;
    int* csr = (int*)p_csr;
    int* deg = (int*)p_deg;
    int* off = (int*)p_off;
    int* cur = (int*)p_cur;
    int* bsum = (int*)p_bsum;

    static bool attr_set = []() {
        cudaFuncSetAttribute(gemm_mma, cudaFuncAttributeMaxDynamicSharedMemorySize, GEMM_SMEM);
        return true;
    }();
    (void)attr_set;

    static cudaStream_t s2 = []() {
        cudaStream_t s;
        cudaStreamCreateWithFlags(&s, cudaStreamNonBlocking);
        return s;
    }();
    static cudaEvent_t evFork = []() {
        cudaEvent_t e; cudaEventCreateWithFlags(&e, cudaEventDisableTiming); return e;
    }();
    static cudaEvent_t evCsr = []() {
        cudaEvent_t e; cudaEventCreateWithFlags(&e, cudaEventDisableTiming); return e;
    }();

    const int EB = (N_EDGES + 255) / 256;
    const int GB = (N_NODES + 127) / 128;
    const int AB = (N_NODES + 7) / 8;

    // ---- fork CSR build to s2 (overlaps with conversions + embed GEMM) ----
    cudaEventRecord(evFork, 0);
    cudaStreamWaitEvent(s2, evFork, 0);
    zero_int_kernel<<<(N_REL * N_NODES + 255) / 256, 256, 0, s2>>>(deg, N_REL * N_NODES);
    hist_all_kernel<<<dim3(EB, N_REL), 256, 0, s2>>>(e0, e1, e2, e3, deg);
    scan_p1<<<dim3(SCAN_NB, N_REL), 256, 0, s2>>>(deg, bsum);
    scan_p2<<<1, 512, 0, s2>>>(bsum);
    scan_p3<<<dim3(SCAN_NB, N_REL), 256, 0, s2>>>(deg, bsum, off, cur);
    fill_all_kernel<<<dim3(EB, N_REL), 256, 0, s2>>>(e0, e1, e2, e3, cur, csr);
    cudaEventRecord(evCsr, s2);

    // ---- main stream: conversions + embed ----
    conv_w_kernel<<<(21 * 128 * 128 + 255) / 256, 256>>>(emb_w, root_w, conv_w, w16);
    conv_x_kernel<<<(N_NODES * IN_FEAT + 255) / 256, 256>>>(x, x16, N_NODES * IN_FEAT);
    gemm_mma<<<dim3(GB, 1), 256, GEMM_SMEM>>>(x16, N_NODES, IN_FEAT, w16,
                                              /*slotArg=*/0, /*mode=*/2, emb_b,
                                              (float*)0, (__half*)0, h16);

    bool joined = false;
    for (int l = 0; l < N_LAYERS; l++) {
        // packed slotArg: high16 = root slot (1+l), low16 = conv base (4+4l, +y gives 5+4l..8+4l)
        int slotArg = ((1 + l) << 16) | (4 + 4 * l);
        gemm_mma<<<dim3(GB, 5), 256, GEMM_SMEM>>>(h16, N_NODES, EMB, w16,
                                                  slotArg, /*mode=*/1,
                                                  root_b + (size_t)l * EMB,
                                                  out_buf, tmp, (__half*)0);
        if (!joined) {
            cudaStreamWaitEvent(0, evCsr, 0);
            joined = true;
        }
        agg_fused_kernel<<<AB, 256>>>(tmp, off, csr, out_buf, h_buf, h16,
                                      (l == N_LAYERS - 1) ? 1 : 0);
    }

    // ---- global add pool ----
    zero_float_kernel<<<(N_GRAPHS * EMB + 255) / 256, 256>>>(out, N_GRAPHS * EMB);
    pool_kernel<<<(N_NODES + 255) / 256, 128>>>(h_buf, batch, out, N_NODES);
}